// round 1
// baseline (speedup 1.0000x reference)
#include <cuda_runtime.h>
#include <math.h>

#define H    8
#define BB   8
#define NN   1024
#define FIN  512
#define FOUT 256
#define ALPHA 0.2f
#define NEGV -1e9f

// Scratch (device globals per harness allocation rules)
__device__ float g_h[(size_t)H * BB * NN * FOUT];   // 67 MB: h[hd][b*N+n][o]
__device__ float g_f1[H * BB * NN];
__device__ float g_f2[H * BB * NN];

// ---------------------------------------------------------------------------
// Kernel 1: h[hd] = x @ W[hd]^T   (M=8192, N=256, K=512 per head)
// 128x128x16 tile, 8x8 micro-tile, 256 threads
// ---------------------------------------------------------------------------
__global__ __launch_bounds__(256) void gemm_h_kernel(const float* __restrict__ x,
                                                     const float* __restrict__ W)
{
    const int hd = blockIdx.z;
    const int m0 = blockIdx.x * 128;
    const int o0 = blockIdx.y * 128;

    __shared__ float As[16][128];
    __shared__ float Bs[16][128];

    const int tid = threadIdx.x;
    const int ty = tid >> 4;          // 0..15
    const int tx = tid & 15;          // 0..15

    float acc[8][8];
#pragma unroll
    for (int i = 0; i < 8; i++)
#pragma unroll
        for (int j = 0; j < 8; j++) acc[i][j] = 0.f;

    const float* Ap = x + (size_t)m0 * FIN;
    const float* Bp = W + (size_t)hd * FOUT * FIN + (size_t)o0 * FIN;

    for (int k0 = 0; k0 < FIN; k0 += 16) {
#pragma unroll
        for (int i = 0; i < 2; i++) {
            int idx = tid + i * 256;       // 0..511
            int row = idx >> 2;            // 0..127
            int c4  = (idx & 3) << 2;      // 0,4,8,12
            float4 va = *(const float4*)(Ap + (size_t)row * FIN + k0 + c4);
            As[c4 + 0][row] = va.x; As[c4 + 1][row] = va.y;
            As[c4 + 2][row] = va.z; As[c4 + 3][row] = va.w;
            float4 vb = *(const float4*)(Bp + (size_t)row * FIN + k0 + c4);
            Bs[c4 + 0][row] = vb.x; Bs[c4 + 1][row] = vb.y;
            Bs[c4 + 2][row] = vb.z; Bs[c4 + 3][row] = vb.w;
        }
        __syncthreads();
#pragma unroll
        for (int kk = 0; kk < 16; kk++) {
            float a[8], b[8];
            *(float4*)&a[0] = *(const float4*)&As[kk][ty * 8];
            *(float4*)&a[4] = *(const float4*)&As[kk][ty * 8 + 4];
            *(float4*)&b[0] = *(const float4*)&Bs[kk][tx * 8];
            *(float4*)&b[4] = *(const float4*)&Bs[kk][tx * 8 + 4];
#pragma unroll
            for (int i = 0; i < 8; i++)
#pragma unroll
                for (int j = 0; j < 8; j++)
                    acc[i][j] = fmaf(a[i], b[j], acc[i][j]);
        }
        __syncthreads();
    }

    float* Cp = g_h + ((size_t)hd * BB * NN + m0) * FOUT + o0;
#pragma unroll
    for (int i = 0; i < 8; i++) {
        float4 v0 = make_float4(acc[i][0], acc[i][1], acc[i][2], acc[i][3]);
        float4 v1 = make_float4(acc[i][4], acc[i][5], acc[i][6], acc[i][7]);
        *(float4*)(Cp + (size_t)(ty * 8 + i) * FOUT + tx * 8)     = v0;
        *(float4*)(Cp + (size_t)(ty * 8 + i) * FOUT + tx * 8 + 4) = v1;
    }
}

// ---------------------------------------------------------------------------
// Kernel 2: f1/f2 = h @ a1 / h @ a2, warp per row
// ---------------------------------------------------------------------------
__global__ __launch_bounds__(256) void f12_kernel(const float* __restrict__ a1,
                                                  const float* __restrict__ a2)
{
    int gw   = (blockIdx.x * 256 + threadIdx.x) >> 5;   // 0..65535
    int lane = threadIdx.x & 31;
    int hd   = gw >> 13;
    const float* hrow = g_h + (size_t)gw * FOUT;
    const float* A1 = a1 + hd * FOUT;
    const float* A2 = a2 + hd * FOUT;
    float s1 = 0.f, s2 = 0.f;
#pragma unroll
    for (int i = 0; i < 8; i++) {
        int o = lane + i * 32;
        float hv = hrow[o];
        s1 = fmaf(hv, A1[o], s1);
        s2 = fmaf(hv, A2[o], s2);
    }
#pragma unroll
    for (int off = 16; off; off >>= 1) {
        s1 += __shfl_xor_sync(0xffffffffu, s1, off);
        s2 += __shfl_xor_sync(0xffffffffu, s2, off);
    }
    if (lane == 0) { g_f1[gw] = s1; g_f2[gw] = s2; }
}

// ---------------------------------------------------------------------------
// Kernel 3: fused attention + elu-sum over heads + log_softmax
// block = (b, 8-row tile); 256 threads (thread = output channel o)
// ---------------------------------------------------------------------------
__global__ __launch_bounds__(256) void attn_kernel(const int* __restrict__ adj,
                                                   float* __restrict__ out)
{
    __shared__ float p_t[NN][8];            // 32 KB, [m][n], 32B stride -> 16B aligned
    __shared__ float f2_s[NN];              // 4 KB
    __shared__ unsigned char msk_t[NN][8];  // 8 KB
    __shared__ float f1_s[8];
    __shared__ float red[8][33];            // padded: bank-conflict-free
    __shared__ float rowmax[8];
    __shared__ float rowstat[8];

    const int b   = blockIdx.y;
    const int n0  = blockIdx.x << 3;
    const int tid = threadIdx.x;
    const int lane = tid & 31;
    const int w    = tid >> 5;
    const int nn   = tid & 7;     // row within tile for e/softmax phases
    const int mb   = tid >> 3;    // 0..31

    // Stage adjacency mask once (reused by all 8 heads). Coalesced global reads.
#pragma unroll
    for (int n = 0; n < 8; n++) {
        const int* arow = adj + ((size_t)b * NN + n0 + n) * NN;
        for (int m = tid; m < NN; m += 256)
            msk_t[m][n] = (unsigned char)(arow[m] == 0);
    }

    float tot[8];
#pragma unroll
    for (int n = 0; n < 8; n++) tot[n] = 0.f;

    for (int hd = 0; hd < H; hd++) {
        const int base = (hd * BB + b) * NN;
        __syncthreads();   // previous head's p_t/f2_s reads done
        for (int m = tid; m < NN; m += 256) f2_s[m] = g_f2[base + m];
        if (tid < 8) f1_s[tid] = g_f1[base + n0 + tid];
        __syncthreads();

        // e = masked leaky(f1 + f2); conflict-free (addresses = tid + 256k)
        float f1v  = f1_s[nn];
        float lmax = -3.0e38f;
#pragma unroll 8
        for (int k = 0; k < 32; k++) {
            int m = mb + (k << 5);
            float e = f1v + f2_s[m];
            e = (e > 0.f) ? e : ALPHA * e;
            if (msk_t[m][nn]) e = NEGV;
            p_t[m][nn] = e;
            lmax = fmaxf(lmax, e);
        }
        red[nn][mb] = lmax;
        __syncthreads();
        if (w < 8) {
            float v = red[w][lane];
#pragma unroll
            for (int off = 16; off; off >>= 1)
                v = fmaxf(v, __shfl_xor_sync(0xffffffffu, v, off));
            if (lane == 0) rowmax[w] = v;
        }
        __syncthreads();

        // exp pass
        float rmax = rowmax[nn];
        float lsum = 0.f;
#pragma unroll 8
        for (int k = 0; k < 32; k++) {
            int m = mb + (k << 5);
            float pv = __expf(p_t[m][nn] - rmax);
            p_t[m][nn] = pv;
            lsum += pv;
        }
        red[nn][mb] = lsum;
        __syncthreads();
        if (w < 8) {
            float v = red[w][lane];
#pragma unroll
            for (int off = 16; off; off >>= 1)
                v += __shfl_xor_sync(0xffffffffu, v, off);
            if (lane == 0) rowstat[w] = 1.f / v;
        }
        __syncthreads();

        // acc[n] = sum_m p[n][m] * h[m][o]   (o = tid)
        const float* hp = g_h + (size_t)base * FOUT + tid;
        float acc[8];
#pragma unroll
        for (int n = 0; n < 8; n++) acc[n] = 0.f;
#pragma unroll 4
        for (int m = 0; m < NN; m++) {
            float hv = __ldg(hp + (size_t)m * FOUT);
            float4 pa = *(const float4*)&p_t[m][0];
            float4 pb = *(const float4*)&p_t[m][4];
            acc[0] = fmaf(pa.x, hv, acc[0]);
            acc[1] = fmaf(pa.y, hv, acc[1]);
            acc[2] = fmaf(pa.z, hv, acc[2]);
            acc[3] = fmaf(pa.w, hv, acc[3]);
            acc[4] = fmaf(pb.x, hv, acc[4]);
            acc[5] = fmaf(pb.y, hv, acc[5]);
            acc[6] = fmaf(pb.z, hv, acc[6]);
            acc[7] = fmaf(pb.w, hv, acc[7]);
        }
#pragma unroll
        for (int n = 0; n < 8; n++) {
            float v = acc[n] * rowstat[n];
            tot[n] += (v > 0.f) ? v : (__expf(v) - 1.f);
        }
    }

    // log_softmax over o (256 threads) for each of the 8 rows
    __syncthreads();
    float wred[8];
#pragma unroll
    for (int n = 0; n < 8; n++) {
        float v = tot[n];
#pragma unroll
        for (int off = 16; off; off >>= 1)
            v = fmaxf(v, __shfl_xor_sync(0xffffffffu, v, off));
        wred[n] = v;
    }
    if (lane < 8) red[lane][w] = wred[lane];
    __syncthreads();
    if (tid < 8) {
        float v = red[tid][0];
#pragma unroll
        for (int j = 1; j < 8; j++) v = fmaxf(v, red[tid][j]);
        rowmax[tid] = v;
    }
    __syncthreads();
#pragma unroll
    for (int n = 0; n < 8; n++) {
        float v = __expf(tot[n] - rowmax[n]);
#pragma unroll
        for (int off = 16; off; off >>= 1)
            v += __shfl_xor_sync(0xffffffffu, v, off);
        wred[n] = v;
    }
    if (lane < 8) red[lane][w] = wred[lane];
    __syncthreads();
    if (tid < 8) {
        float v = red[tid][0];
#pragma unroll
        for (int j = 1; j < 8; j++) v += red[tid][j];
        rowstat[tid] = logf(v);
    }
    __syncthreads();
#pragma unroll
    for (int n = 0; n < 8; n++) {
        out[((size_t)b * NN + n0 + n) * FOUT + tid] = tot[n] - rowmax[n] - rowstat[n];
    }
}

// ---------------------------------------------------------------------------
extern "C" void kernel_launch(void* const* d_in, const int* in_sizes, int n_in,
                              void* d_out, int out_size)
{
    const float* x   = (const float*)d_in[0];
    const int*   adj = (const int*)d_in[1];
    const float* W   = (const float*)d_in[2];
    const float* a1  = (const float*)d_in[3];
    const float* a2  = (const float*)d_in[4];
    float* out = (float*)d_out;

    (void)in_sizes; (void)n_in; (void)out_size;

    gemm_h_kernel<<<dim3(64, 2, 8), 256>>>(x, W);
    f12_kernel<<<8192, 256>>>(a1, a2);
    attn_kernel<<<dim3(128, 8), 256>>>(adj, out);
}

// round 2
// speedup vs baseline: 1.1700x; 1.1700x over previous
#include <cuda_runtime.h>
#include <math.h>

#define H    8
#define BB   8
#define NN   1024
#define FIN  512
#define FOUT 256
#define RR   16            // attention rows per block
#define ALPHA 0.2f
#define NEGV -1e9f

typedef unsigned long long u64;

// Scratch (device globals per harness allocation rules)
__device__ float g_h[(size_t)H * BB * NN * FOUT];   // 67 MB: h[hd][b*N+n][o]
__device__ float g_f1[H * BB * NN];
__device__ float g_f2[H * BB * NN];

// ---- packed f32x2 helpers -------------------------------------------------
#define FFMA2(d, a, b) asm volatile("fma.rn.f32x2 %0, %1, %2, %0;" : "+l"(d) : "l"(a), "l"(b))
#define DUP2(d, s)     asm volatile("mov.b64 %0, {%1, %1};" : "=l"(d) : "f"(s))
#define UNPACK2(lo, hi, v) asm volatile("mov.b64 {%0, %1}, %2;" : "=f"(lo), "=f"(hi) : "l"(v))
#define LDS_V2(a, b, addr) asm volatile("ld.shared.v2.b64 {%0, %1}, [%2];" : "=l"(a), "=l"(b) : "r"(addr))

// ---------------------------------------------------------------------------
// Kernel 1: h[hd] = x @ W[hd]^T   (M=8192, N=256, K=512 per head)
// 128x128x16 tile, 8x8 micro-tile packed as 8x4 f32x2, 256 threads
// ---------------------------------------------------------------------------
__global__ __launch_bounds__(256) void gemm_h_kernel(const float* __restrict__ x,
                                                     const float* __restrict__ W)
{
    const int hd = blockIdx.z;
    const int m0 = blockIdx.x * 128;
    const int o0 = blockIdx.y * 128;

    __shared__ float As[16][128];
    __shared__ float Bs[16][128];

    const int tid = threadIdx.x;
    const int ty = tid >> 4;          // 0..15
    const int tx = tid & 15;          // 0..15

    u64 acc[8][4];
#pragma unroll
    for (int i = 0; i < 8; i++)
#pragma unroll
        for (int j = 0; j < 4; j++) acc[i][j] = 0ull;

    const float* Ap = x + (size_t)m0 * FIN;
    const float* Bp = W + (size_t)hd * FOUT * FIN + (size_t)o0 * FIN;

    const unsigned bs_base = (unsigned)__cvta_generic_to_shared(&Bs[0][0]);

    for (int k0 = 0; k0 < FIN; k0 += 16) {
#pragma unroll
        for (int i = 0; i < 2; i++) {
            int idx = tid + i * 256;       // 0..511
            int row = idx >> 2;            // 0..127
            int c4  = (idx & 3) << 2;      // 0,4,8,12
            float4 va = *(const float4*)(Ap + (size_t)row * FIN + k0 + c4);
            As[c4 + 0][row] = va.x; As[c4 + 1][row] = va.y;
            As[c4 + 2][row] = va.z; As[c4 + 3][row] = va.w;
            float4 vb = *(const float4*)(Bp + (size_t)row * FIN + k0 + c4);
            Bs[c4 + 0][row] = vb.x; Bs[c4 + 1][row] = vb.y;
            Bs[c4 + 2][row] = vb.z; Bs[c4 + 3][row] = vb.w;
        }
        __syncthreads();
#pragma unroll
        for (int kk = 0; kk < 16; kk++) {
            float a[8];
            *(float4*)&a[0] = *(const float4*)&As[kk][ty * 8];
            *(float4*)&a[4] = *(const float4*)&As[kk][ty * 8 + 4];
            u64 b[4];
            unsigned baddr = bs_base + (unsigned)((kk * 128 + tx * 8) * 4);
            LDS_V2(b[0], b[1], baddr);
            LDS_V2(b[2], b[3], baddr + 16);
            u64 ad[8];
#pragma unroll
            for (int i = 0; i < 8; i++) DUP2(ad[i], a[i]);
#pragma unroll
            for (int i = 0; i < 8; i++)
#pragma unroll
                for (int j = 0; j < 4; j++)
                    FFMA2(acc[i][j], ad[i], b[j]);
        }
        __syncthreads();
    }

    float* Cp = g_h + ((size_t)hd * BB * NN + m0) * FOUT + o0;
#pragma unroll
    for (int i = 0; i < 8; i++) {
        u64* dst = (u64*)(Cp + (size_t)(ty * 8 + i) * FOUT + tx * 8);
        dst[0] = acc[i][0]; dst[1] = acc[i][1];
        dst[2] = acc[i][2]; dst[3] = acc[i][3];
    }
}

// ---------------------------------------------------------------------------
// Kernel 2: f1/f2 = h @ a1 / h @ a2, warp per row
// ---------------------------------------------------------------------------
__global__ __launch_bounds__(256) void f12_kernel(const float* __restrict__ a1,
                                                  const float* __restrict__ a2)
{
    int gw   = (blockIdx.x * 256 + threadIdx.x) >> 5;   // 0..65535
    int lane = threadIdx.x & 31;
    int hd   = gw >> 13;
    const float* hrow = g_h + (size_t)gw * FOUT;
    const float* A1 = a1 + hd * FOUT;
    const float* A2 = a2 + hd * FOUT;
    float s1 = 0.f, s2 = 0.f;
#pragma unroll
    for (int i = 0; i < 8; i++) {
        int o = lane + i * 32;
        float hv = hrow[o];
        s1 = fmaf(hv, A1[o], s1);
        s2 = fmaf(hv, A2[o], s2);
    }
#pragma unroll
    for (int off = 16; off; off >>= 1) {
        s1 += __shfl_xor_sync(0xffffffffu, s1, off);
        s2 += __shfl_xor_sync(0xffffffffu, s2, off);
    }
    if (lane == 0) { g_f1[gw] = s1; g_f2[gw] = s2; }
}

// ---------------------------------------------------------------------------
// Kernel 3: fused attention + elu-sum over heads + log_softmax
// block = (b, 16-row tile); 256 threads (thread = output channel o)
// dynamic smem layout:
//   [0, 65536)        p2: u64[NN][8]  (f32x2 pairs over row dim)
//   [65536, 69632)    f2_s: float[NN]
//   [69632, 86016)    msk: uchar[NN][16]
//   [86016, 86080)    f1_s: float[16]
//   [86080, 87168)    red: float[16][17]
//   [87168, 87232)    rowmax[16]
//   [87232, 87296)    rowstat[16]
// ---------------------------------------------------------------------------
#define SM_P2   0
#define SM_F2   65536
#define SM_MSK  69632
#define SM_F1   86016
#define SM_RED  86080
#define SM_RMAX 87168
#define SM_RST  87232
#define SM_TOTAL 87296

__global__ __launch_bounds__(256, 2) void attn_kernel(const int* __restrict__ adj,
                                                      float* __restrict__ out)
{
    extern __shared__ char smem[];
    float*         pf      = (float*)(smem + SM_P2);
    float*         f2_s    = (float*)(smem + SM_F2);
    unsigned char* msk     = (unsigned char*)(smem + SM_MSK);
    float*         f1_s    = (float*)(smem + SM_F1);
    float*         red     = (float*)(smem + SM_RED);
    float*         rowmax  = (float*)(smem + SM_RMAX);
    float*         rowstat = (float*)(smem + SM_RST);

    const unsigned pbase = (unsigned)__cvta_generic_to_shared(smem + SM_P2);

    const int b   = blockIdx.y;
    const int n0  = blockIdx.x * RR;
    const int tid = threadIdx.x;
    const int lane = tid & 31;
    const int w    = tid >> 5;
    const int nn   = tid & 15;    // row within tile (softmax phases)
    const int mb   = tid >> 4;    // 0..15

    // Stage adjacency mask once (reused by all 8 heads). Coalesced global reads.
#pragma unroll
    for (int n = 0; n < RR; n++) {
        const int* arow = adj + ((size_t)b * NN + n0 + n) * NN;
        for (int m = tid; m < NN; m += 256)
            msk[m * RR + n] = (unsigned char)(arow[m] == 0);
    }

    float tot[RR];
#pragma unroll
    for (int n = 0; n < RR; n++) tot[n] = 0.f;

    for (int hd = 0; hd < H; hd++) {
        const int base = (hd * BB + b) * NN;
        __syncthreads();   // previous head's p2/f2_s reads done
        for (int m = tid; m < NN; m += 256) f2_s[m] = g_f2[base + m];
        if (tid < RR) f1_s[tid] = g_f1[base + n0 + tid];
        __syncthreads();

        // e = masked leaky(f1 + f2); conflict-free writes (see bank analysis)
        float f1v  = f1_s[nn];
        float lmax = -3.0e38f;
#pragma unroll 8
        for (int k = 0; k < 64; k++) {
            int m = mb + (k << 4);
            float e = f1v + f2_s[m];
            e = (e > 0.f) ? e : ALPHA * e;
            if (msk[m * RR + nn]) e = NEGV;
            pf[m * RR + nn] = e;
            lmax = fmaxf(lmax, e);
        }
        red[nn * 17 + mb] = lmax;
        __syncthreads();
        if (tid < RR) {
            float v = red[tid * 17];
#pragma unroll
            for (int j = 1; j < 16; j++) v = fmaxf(v, red[tid * 17 + j]);
            rowmax[tid] = v;
        }
        __syncthreads();

        // exp pass
        float rmax = rowmax[nn];
        float lsum = 0.f;
#pragma unroll 8
        for (int k = 0; k < 64; k++) {
            int m = mb + (k << 4);
            float pv = __expf(pf[m * RR + nn] - rmax);
            pf[m * RR + nn] = pv;
            lsum += pv;
        }
        red[nn * 17 + mb] = lsum;
        __syncthreads();
        if (tid < RR) {
            float v = red[tid * 17];
#pragma unroll
            for (int j = 1; j < 16; j++) v += red[tid * 17 + j];
            rowstat[tid] = 1.f / v;
        }
        __syncthreads();

        // acc[pair n] += p[n][m] * h[m][o]   (o = tid), packed f32x2 over n
        const float* hp = g_h + (size_t)base * FOUT + tid;
        u64 acc[8];
#pragma unroll
        for (int j = 0; j < 8; j++) acc[j] = 0ull;

        for (int m0 = 0; m0 < NN; m0 += 4) {
            float h0 = __ldg(hp + (size_t)(m0 + 0) * FOUT);
            float h1 = __ldg(hp + (size_t)(m0 + 1) * FOUT);
            float h2 = __ldg(hp + (size_t)(m0 + 2) * FOUT);
            float h3 = __ldg(hp + (size_t)(m0 + 3) * FOUT);
#pragma unroll
            for (int q = 0; q < 4; q++) {
                float hv = (q == 0) ? h0 : (q == 1) ? h1 : (q == 2) ? h2 : h3;
                u64 hd2;
                DUP2(hd2, hv);
                unsigned addr = pbase + (unsigned)((m0 + q) * (RR * 4));
                u64 p0, p1, p2v, p3;
                LDS_V2(p0, p1, addr);
                LDS_V2(p2v, p3, addr + 16);
                FFMA2(acc[0], p0, hd2);
                FFMA2(acc[1], p1, hd2);
                FFMA2(acc[2], p2v, hd2);
                FFMA2(acc[3], p3, hd2);
                u64 p4, p5, p6, p7;
                LDS_V2(p4, p5, addr + 32);
                LDS_V2(p6, p7, addr + 48);
                FFMA2(acc[4], p4, hd2);
                FFMA2(acc[5], p5, hd2);
                FFMA2(acc[6], p6, hd2);
                FFMA2(acc[7], p7, hd2);
            }
        }
#pragma unroll
        for (int j = 0; j < 8; j++) {
            float lo, hi;
            UNPACK2(lo, hi, acc[j]);
            float v0 = lo * rowstat[2 * j];
            float v1 = hi * rowstat[2 * j + 1];
            tot[2 * j]     += (v0 > 0.f) ? v0 : (__expf(v0) - 1.f);
            tot[2 * j + 1] += (v1 > 0.f) ? v1 : (__expf(v1) - 1.f);
        }
    }

    // log_softmax over o (256 threads) for each of the 16 rows
    __syncthreads();
#pragma unroll
    for (int n = 0; n < RR; n++) {
        float v = tot[n];
#pragma unroll
        for (int off = 16; off; off >>= 1)
            v = fmaxf(v, __shfl_xor_sync(0xffffffffu, v, off));
        if (lane == 0) red[n * 17 + w] = v;
    }
    __syncthreads();
    if (tid < RR) {
        float v = red[tid * 17];
#pragma unroll
        for (int j = 1; j < 8; j++) v = fmaxf(v, red[tid * 17 + j]);
        rowmax[tid] = v;
    }
    __syncthreads();
#pragma unroll
    for (int n = 0; n < RR; n++) {
        float v = __expf(tot[n] - rowmax[n]);
#pragma unroll
        for (int off = 16; off; off >>= 1)
            v += __shfl_xor_sync(0xffffffffu, v, off);
        if (lane == 0) red[n * 17 + w] = v;
    }
    __syncthreads();
    if (tid < RR) {
        float v = red[tid * 17];
#pragma unroll
        for (int j = 1; j < 8; j++) v += red[tid * 17 + j];
        rowstat[tid] = logf(v);
    }
    __syncthreads();
#pragma unroll
    for (int n = 0; n < RR; n++) {
        out[((size_t)b * NN + n0 + n) * FOUT + tid] = tot[n] - rowmax[n] - rowstat[n];
    }
}

// ---------------------------------------------------------------------------
extern "C" void kernel_launch(void* const* d_in, const int* in_sizes, int n_in,
                              void* d_out, int out_size)
{
    const float* x   = (const float*)d_in[0];
    const int*   adj = (const int*)d_in[1];
    const float* W   = (const float*)d_in[2];
    const float* a1  = (const float*)d_in[3];
    const float* a2  = (const float*)d_in[4];
    float* out = (float*)d_out;

    (void)in_sizes; (void)n_in; (void)out_size;

    cudaFuncSetAttribute(attn_kernel, cudaFuncAttributeMaxDynamicSharedMemorySize, SM_TOTAL);

    gemm_h_kernel<<<dim3(64, 2, 8), 256>>>(x, W);
    f12_kernel<<<8192, 256>>>(a1, a2);
    attn_kernel<<<dim3(64, 8), 256, SM_TOTAL>>>(adj, out);
}

// round 10
// speedup vs baseline: 1.4140x; 1.2086x over previous
#include <cuda_runtime.h>
#include <cuda_bf16.h>
#include <math.h>
#include <cstdint>

#define H    8
#define BB   8
#define NN   1024
#define FIN  512
#define FOUT 256
#define RR   16
#define ALPHA 0.2f

typedef unsigned long long u64;

// Scratch (device globals per harness allocation rules)
__device__ float g_h[(size_t)H * BB * NN * FOUT];   // 67 MB
__device__ float g_f1[H * BB * NN];
__device__ float g_f2[H * BB * NN];
__device__ __nv_bfloat16 g_xh[(size_t)BB * NN * FIN];
__device__ __nv_bfloat16 g_xl[(size_t)BB * NN * FIN];
__device__ __nv_bfloat16 g_wh[(size_t)H * FOUT * FIN];
__device__ __nv_bfloat16 g_wl[(size_t)H * FOUT * FIN];

// ---- packed f32x2 helpers -------------------------------------------------
#define FFMA2(d, a, b) asm volatile("fma.rn.f32x2 %0, %1, %2, %0;" : "+l"(d) : "l"(a), "l"(b))
#define DUP2(d, s)     asm volatile("mov.b64 %0, {%1, %1};" : "=l"(d) : "f"(s))
#define UNPACK2(lo, hi, v) asm volatile("mov.b64 {%0, %1}, %2;" : "=f"(lo), "=f"(hi) : "l"(v))
#define LDS_V2(a, b, addr) asm volatile("ld.shared.v2.b64 {%0, %1}, [%2];" : "=l"(a), "=l"(b) : "r"(addr))

// ---- ldmatrix / mma.sync helpers (sm_80-era PTX, valid on plain sm_103) ---
__device__ __forceinline__ uint32_t smem_u32(const void* p) {
    uint32_t a;
    asm("{ .reg .u64 t; cvta.to.shared.u64 t, %1; cvt.u32.u64 %0, t; }" : "=r"(a) : "l"(p));
    return a;
}
#define LDMX4(r0, r1, r2, r3, a) \
    asm volatile("ldmatrix.sync.aligned.m8n8.x4.shared.b16 {%0,%1,%2,%3}, [%4];" \
                 : "=r"(r0), "=r"(r1), "=r"(r2), "=r"(r3) : "r"(a))
#define MMA16816(d, a0, a1, a2, a3, b0, b1) \
    asm volatile("mma.sync.aligned.m16n8k16.row.col.f32.bf16.bf16.f32 " \
                 "{%0,%1,%2,%3},{%4,%5,%6,%7},{%8,%9},{%0,%1,%2,%3};" \
                 : "+f"((d)[0]), "+f"((d)[1]), "+f"((d)[2]), "+f"((d)[3]) \
                 : "r"(a0), "r"(a1), "r"(a2), "r"(a3), "r"(b0), "r"(b1))

// swizzled smem address: 128B rows, 16B chunk xor (row&7)
__device__ __forceinline__ uint32_t lmaddr(uint32_t base, int row, int chunk) {
    return base + row * 128 + (((chunk) ^ (row & 7)) << 4);
}

// ---------------------------------------------------------------------------
// Kernel 0: split x and W into bf16 hi/lo pairs
// ---------------------------------------------------------------------------
__global__ __launch_bounds__(256) void split_kernel(const float* __restrict__ x,
                                                    const float* __restrict__ W)
{
    const size_t NX = (size_t)BB * NN * FIN;
    const size_t NW = (size_t)H * FOUT * FIN;
    size_t i = (size_t)blockIdx.x * 256 + threadIdx.x;
    size_t stride = (size_t)gridDim.x * 256;
    for (; i < NX + NW; i += stride) {
        if (i < NX) {
            float v = x[i];
            __nv_bfloat16 hi = __float2bfloat16_rn(v);
            __nv_bfloat16 lo = __float2bfloat16_rn(v - __bfloat162float(hi));
            g_xh[i] = hi; g_xl[i] = lo;
        } else {
            size_t j = i - NX;
            float v = W[j];
            __nv_bfloat16 hi = __float2bfloat16_rn(v);
            __nv_bfloat16 lo = __float2bfloat16_rn(v - __bfloat162float(hi));
            g_wh[j] = hi; g_wl[j] = lo;
        }
    }
}

// ---------------------------------------------------------------------------
// Kernel 1: h[hd] = x @ W[hd]^T via mma.sync bf16 split-3
// block: 256 thr (8 warps, 4m x 2n), tile 128(M) x 128(O), k-chunk 64
// ---------------------------------------------------------------------------
#define GA_H 0
#define GA_L 16384
#define GB_H 32768
#define GB_L 49152
#define G_TOTAL 65536

__global__ __launch_bounds__(256) void gemm_h_mma(void)
{
    extern __shared__ char sm[];
    const uint32_t sb = smem_u32(sm);
    const int tid = threadIdx.x;
    const int wid = tid >> 5;
    const int lane = tid & 31;
    const int m0 = blockIdx.x * 128;
    const int o0 = blockIdx.y * 128;
    const int hd = blockIdx.z;
    const int warp_m = (wid & 3) * 32;
    const int warp_n = (wid >> 2) * 64;

    float d[2][8][4];
#pragma unroll
    for (int i = 0; i < 2; i++)
#pragma unroll
        for (int j = 0; j < 8; j++)
#pragma unroll
            for (int c = 0; c < 4; c++) d[i][j][c] = 0.f;

    const char* xh = (const char*)g_xh + (size_t)m0 * FIN * 2;
    const char* xl = (const char*)g_xl + (size_t)m0 * FIN * 2;
    const char* wh = (const char*)g_wh + ((size_t)hd * FOUT + o0) * FIN * 2;
    const char* wl = (const char*)g_wl + ((size_t)hd * FOUT + o0) * FIN * 2;

    // ldmatrix lane addressing precompute
    const int lt = lane >> 3;        // tile 0..3
    const int lr = lane & 7;         // row-in-tile

    for (int kc = 0; kc < FIN; kc += 64) {
        __syncthreads();
        // stage 4 tiles: each 128 rows x 64 bf16 (16KB), uint4 chunks
#pragma unroll
        for (int it = 0; it < 4; it++) {
            int idx = tid + it * 256;          // 0..1023
            int r = idx >> 3, ch = idx & 7;
            size_t gb = ((size_t)r * FIN + kc) * 2 + ch * 16;
            uint32_t so = (uint32_t)(r * 128 + ((ch ^ (r & 7)) << 4));
            *(uint4*)(sm + GA_H + so) = *(const uint4*)(xh + gb);
            *(uint4*)(sm + GA_L + so) = *(const uint4*)(xl + gb);
            *(uint4*)(sm + GB_H + so) = *(const uint4*)(wh + gb);
            *(uint4*)(sm + GB_L + so) = *(const uint4*)(wl + gb);
        }
        __syncthreads();

#pragma unroll
        for (int kk = 0; kk < 64; kk += 16) {
            const int kch = kk >> 3;
            // A fragments hi/lo for both m16 tiles
            uint32_t ah[2][4], al[2][4];
#pragma unroll
            for (int mi = 0; mi < 2; mi++) {
                int row = warp_m + mi * 16 + (lt & 1) * 8 + lr;
                uint32_t ad = lmaddr(sb + GA_H, row, kch + (lt >> 1));
                LDMX4(ah[mi][0], ah[mi][1], ah[mi][2], ah[mi][3], ad);
                uint32_t ad2 = lmaddr(sb + GA_L, row, kch + (lt >> 1));
                LDMX4(al[mi][0], al[mi][1], al[mi][2], al[mi][3], ad2);
            }
#pragma unroll
            for (int pr = 0; pr < 4; pr++) {
                int row = warp_n + pr * 16 + (lt & 1) * 8 + lr;
                uint32_t bh0, bh1, bh2, bh3, bl0, bl1, bl2, bl3;
                LDMX4(bh0, bh1, bh2, bh3, lmaddr(sb + GB_H, row, kch + (lt >> 1)));
                LDMX4(bl0, bl1, bl2, bl3, lmaddr(sb + GB_L, row, kch + (lt >> 1)));
#pragma unroll
                for (int mi = 0; mi < 2; mi++) {
                    // Ah*Bh
                    MMA16816(d[mi][2 * pr],     ah[mi][0], ah[mi][1], ah[mi][2], ah[mi][3], bh0, bh2);
                    MMA16816(d[mi][2 * pr + 1], ah[mi][0], ah[mi][1], ah[mi][2], ah[mi][3], bh1, bh3);
                    // Ah*Bl
                    MMA16816(d[mi][2 * pr],     ah[mi][0], ah[mi][1], ah[mi][2], ah[mi][3], bl0, bl2);
                    MMA16816(d[mi][2 * pr + 1], ah[mi][0], ah[mi][1], ah[mi][2], ah[mi][3], bl1, bl3);
                    // Al*Bh
                    MMA16816(d[mi][2 * pr],     al[mi][0], al[mi][1], al[mi][2], al[mi][3], bh0, bh2);
                    MMA16816(d[mi][2 * pr + 1], al[mi][0], al[mi][1], al[mi][2], al[mi][3], bh1, bh3);
                }
            }
        }
    }

    // epilogue: thread (g,t) owns rows g,(g+8), cols 2t,2t+1 of each 16x8 tile
    const int g = lane >> 2, t = lane & 3;
    float* hb = g_h + (size_t)hd * BB * NN * FOUT;
#pragma unroll
    for (int mi = 0; mi < 2; mi++) {
#pragma unroll
        for (int nj = 0; nj < 8; nj++) {
            int row = m0 + warp_m + mi * 16 + g;
            int col = o0 + warp_n + nj * 8 + 2 * t;
            float* p0 = hb + (size_t)row * FOUT + col;
            p0[0] = d[mi][nj][0];
            p0[1] = d[mi][nj][1];
            float* p1 = p0 + 8 * FOUT;
            p1[0] = d[mi][nj][2];
            p1[1] = d[mi][nj][3];
        }
    }
}

// ---------------------------------------------------------------------------
// Kernel 2: f1/f2 = h @ a1 / h @ a2, warp per row
// ---------------------------------------------------------------------------
__global__ __launch_bounds__(256) void f12_kernel(const float* __restrict__ a1,
                                                  const float* __restrict__ a2)
{
    int gw   = (blockIdx.x * 256 + threadIdx.x) >> 5;
    int lane = threadIdx.x & 31;
    int hd   = gw >> 13;
    const float* hrow = g_h + (size_t)gw * FOUT;
    const float* A1 = a1 + hd * FOUT;
    const float* A2 = a2 + hd * FOUT;
    float s1 = 0.f, s2 = 0.f;
#pragma unroll
    for (int i = 0; i < 8; i++) {
        int o = lane + i * 32;
        float hv = hrow[o];
        s1 = fmaf(hv, A1[o], s1);
        s2 = fmaf(hv, A2[o], s2);
    }
#pragma unroll
    for (int off = 16; off; off >>= 1) {
        s1 += __shfl_xor_sync(0xffffffffu, s1, off);
        s2 += __shfl_xor_sync(0xffffffffu, s2, off);
    }
    if (lane == 0) { g_f1[gw] = s1; g_f2[gw] = s2; }
}

// ---------------------------------------------------------------------------
// Kernel 3: fused attention (single-pass softmax) + elu-sum + log_softmax
// ---------------------------------------------------------------------------
#define SM_P2   0
#define SM_F2   65536
#define SM_MSK  69632
#define SM_F1   86016
#define SM_RED  86080
#define SM_RMAX 87168
#define SM_RST  87232
#define SM_TOTAL 87296

__global__ __launch_bounds__(256, 2) void attn_kernel(const int* __restrict__ adj,
                                                      float* __restrict__ out)
{
    extern __shared__ char smem[];
    float*         pf      = (float*)(smem + SM_P2);
    float*         f2_s    = (float*)(smem + SM_F2);
    unsigned char* msk     = (unsigned char*)(smem + SM_MSK);
    float*         f1_s    = (float*)(smem + SM_F1);
    float*         red     = (float*)(smem + SM_RED);
    float*         rowmax  = (float*)(smem + SM_RMAX);
    float*         rowstat = (float*)(smem + SM_RST);

    const uint32_t pbase = smem_u32(smem + SM_P2);

    const int b   = blockIdx.y;
    const int n0  = blockIdx.x * RR;
    const int tid = threadIdx.x;
    const int lane = tid & 31;
    const int w    = tid >> 5;
    const int nn   = tid & 15;
    const int mb   = tid >> 4;

#pragma unroll
    for (int n = 0; n < RR; n++) {
        const int* arow = adj + ((size_t)b * NN + n0 + n) * NN;
        for (int m = tid; m < NN; m += 256)
            msk[m * RR + n] = (unsigned char)(arow[m] == 0);
    }

    float tot[RR];
#pragma unroll
    for (int n = 0; n < RR; n++) tot[n] = 0.f;

    for (int hd = 0; hd < H; hd++) {
        const int base = (hd * BB + b) * NN;
        __syncthreads();
        for (int m = tid; m < NN; m += 256) f2_s[m] = g_f2[base + m];
        if (tid < RR) f1_s[tid] = g_f1[base + n0 + tid];
        __syncthreads();

        // single pass: p = exp(masked leaky(f1+f2)); row sums
        float f1v  = f1_s[nn];
        float lsum = 0.f;
#pragma unroll 8
        for (int k = 0; k < 64; k++) {
            int m = mb + (k << 4);
            float e = f1v + f2_s[m];
            e = (e > 0.f) ? e : ALPHA * e;
            float pv = msk[m * RR + nn] ? 0.f : __expf(e);
            pf[m * RR + nn] = pv;
            lsum += pv;
        }
        red[nn * 17 + mb] = lsum;
        __syncthreads();
        if (tid < RR) {
            float v = red[tid * 17];
#pragma unroll
            for (int j = 1; j < 16; j++) v += red[tid * 17 + j];
            rowstat[tid] = 1.f / v;
        }
        __syncthreads();

        // acc[pair n] += p[n][m] * h[m][o]  (o = tid), f32x2, prefetched
        const float* hp = g_h + (size_t)base * FOUT + tid;
        u64 acc[8];
#pragma unroll
        for (int j = 0; j < 8; j++) acc[j] = 0ull;

        float cur0 = __ldg(hp), cur1 = __ldg(hp + FOUT);
        float cur2 = __ldg(hp + 2 * FOUT), cur3 = __ldg(hp + 3 * FOUT);

        for (int m0 = 0; m0 < NN; m0 += 4) {
            float nx0, nx1, nx2, nx3;
            if (m0 + 4 < NN) {
                const float* np = hp + (size_t)(m0 + 4) * FOUT;
                nx0 = __ldg(np); nx1 = __ldg(np + FOUT);
                nx2 = __ldg(np + 2 * FOUT); nx3 = __ldg(np + 3 * FOUT);
            } else { nx0 = nx1 = nx2 = nx3 = 0.f; }
#pragma unroll
            for (int q = 0; q < 4; q++) {
                float hv = (q == 0) ? cur0 : (q == 1) ? cur1 : (q == 2) ? cur2 : cur3;
                u64 hd2;
                DUP2(hd2, hv);
                unsigned addr = pbase + (unsigned)((m0 + q) * (RR * 4));
                u64 p0, p1, p2v, p3;
                LDS_V2(p0, p1, addr);
                LDS_V2(p2v, p3, addr + 16);
                FFMA2(acc[0], p0, hd2);
                FFMA2(acc[1], p1, hd2);
                FFMA2(acc[2], p2v, hd2);
                FFMA2(acc[3], p3, hd2);
                u64 p4, p5, p6, p7;
                LDS_V2(p4, p5, addr + 32);
                LDS_V2(p6, p7, addr + 48);
                FFMA2(acc[4], p4, hd2);
                FFMA2(acc[5], p5, hd2);
                FFMA2(acc[6], p6, hd2);
                FFMA2(acc[7], p7, hd2);
            }
            cur0 = nx0; cur1 = nx1; cur2 = nx2; cur3 = nx3;
        }
#pragma unroll
        for (int j = 0; j < 8; j++) {
            float lo, hi;
            UNPACK2(lo, hi, acc[j]);
            float v0 = lo * rowstat[2 * j];
            float v1 = hi * rowstat[2 * j + 1];
            tot[2 * j]     += (v0 > 0.f) ? v0 : (__expf(v0) - 1.f);
            tot[2 * j + 1] += (v1 > 0.f) ? v1 : (__expf(v1) - 1.f);
        }
    }

    // log_softmax over o for the 16 rows
    __syncthreads();
#pragma unroll
    for (int n = 0; n < RR; n++) {
        float v = tot[n];
#pragma unroll
        for (int off = 16; off; off >>= 1)
            v = fmaxf(v, __shfl_xor_sync(0xffffffffu, v, off));
        if (lane == 0) red[n * 17 + w] = v;
    }
    __syncthreads();
    if (tid < RR) {
        float v = red[tid * 17];
#pragma unroll
        for (int j = 1; j < 8; j++) v = fmaxf(v, red[tid * 17 + j]);
        rowmax[tid] = v;
    }
    __syncthreads();
#pragma unroll
    for (int n = 0; n < RR; n++) {
        float v = __expf(tot[n] - rowmax[n]);
#pragma unroll
        for (int off = 16; off; off >>= 1)
            v += __shfl_xor_sync(0xffffffffu, v, off);
        if (lane == 0) red[n * 17 + w] = v;
    }
    __syncthreads();
    if (tid < RR) {
        float v = red[tid * 17];
#pragma unroll
        for (int j = 1; j < 8; j++) v += red[tid * 17 + j];
        rowstat[tid] = logf(v);
    }
    __syncthreads();
#pragma unroll
    for (int n = 0; n < RR; n++) {
        out[((size_t)b * NN + n0 + n) * FOUT + tid] = tot[n] - rowmax[n] - rowstat[n];
    }
}

// ---------------------------------------------------------------------------
extern "C" void kernel_launch(void* const* d_in, const int* in_sizes, int n_in,
                              void* d_out, int out_size)
{
    const float* x   = (const float*)d_in[0];
    const int*   adj = (const int*)d_in[1];
    const float* W   = (const float*)d_in[2];
    const float* a1  = (const float*)d_in[3];
    const float* a2  = (const float*)d_in[4];
    float* out = (float*)d_out;

    (void)in_sizes; (void)n_in; (void)out_size;

    cudaFuncSetAttribute(gemm_h_mma, cudaFuncAttributeMaxDynamicSharedMemorySize, G_TOTAL);
    cudaFuncSetAttribute(attn_kernel, cudaFuncAttributeMaxDynamicSharedMemorySize, SM_TOTAL);

    split_kernel<<<2560, 256>>>(x, W);
    gemm_h_mma<<<dim3(64, 2, 8), 256, G_TOTAL>>>();
    f12_kernel<<<8192, 256>>>(a1, a2);
    attn_kernel<<<dim3(64, 8), 256, SM_TOTAL>>>(adj, out);
}

// round 12
// speedup vs baseline: 5.2259x; 3.6959x over previous
#include <cuda_runtime.h>
#include <cuda_bf16.h>
#include <math.h>
#include <cstdint>

#define H    8
#define BB   8
#define NN   1024
#define FIN  512
#define FOUT 256
#define ALPHA 0.2f

typedef unsigned long long u64;

// Scratch (device globals per harness allocation rules)
__device__ float g_f1[H * BB * NN];
__device__ float g_f2[H * BB * NN];
__device__ __nv_bfloat16 g_xh[(size_t)BB * NN * FIN];
__device__ __nv_bfloat16 g_xl[(size_t)BB * NN * FIN];
__device__ __nv_bfloat16 g_wh[(size_t)H * FOUT * FIN];
__device__ __nv_bfloat16 g_wl[(size_t)H * FOUT * FIN];
__device__ __nv_bfloat16 g_hh[(size_t)H * BB * NN * FOUT];   // h bf16 hi
__device__ __nv_bfloat16 g_hl[(size_t)H * BB * NN * FOUT];   // h bf16 lo

// ---- ldmatrix / mma.sync helpers (sm_80-era PTX, valid on plain sm_103) ---
__device__ __forceinline__ uint32_t smem_u32(const void* p) {
    uint32_t a;
    asm("{ .reg .u64 t; cvta.to.shared.u64 t, %1; cvt.u32.u64 %0, t; }" : "=r"(a) : "l"(p));
    return a;
}
#define LDMX4(r0, r1, r2, r3, a) \
    asm volatile("ldmatrix.sync.aligned.m8n8.x4.shared.b16 {%0,%1,%2,%3}, [%4];" \
                 : "=r"(r0), "=r"(r1), "=r"(r2), "=r"(r3) : "r"(a))
#define LDMX4T(r0, r1, r2, r3, a) \
    asm volatile("ldmatrix.sync.aligned.m8n8.x4.trans.shared.b16 {%0,%1,%2,%3}, [%4];" \
                 : "=r"(r0), "=r"(r1), "=r"(r2), "=r"(r3) : "r"(a))
#define MMA16816(d, a0, a1, a2, a3, b0, b1) \
    asm volatile("mma.sync.aligned.m16n8k16.row.col.f32.bf16.bf16.f32 " \
                 "{%0,%1,%2,%3},{%4,%5,%6,%7},{%8,%9},{%0,%1,%2,%3};" \
                 : "+f"((d)[0]), "+f"((d)[1]), "+f"((d)[2]), "+f"((d)[3]) \
                 : "r"(a0), "r"(a1), "r"(a2), "r"(a3), "r"(b0), "r"(b1))
#define CPA16(dst, src) \
    asm volatile("cp.async.cg.shared.global [%0], [%1], 16;" :: "r"(dst), "l"(src) : "memory")
#define CP_COMMIT() asm volatile("cp.async.commit_group;" ::: "memory")
#define CP_WAIT0()  asm volatile("cp.async.wait_group 0;" ::: "memory")
#define CP_WAIT1()  asm volatile("cp.async.wait_group 1;" ::: "memory")

__device__ __forceinline__ uint32_t lmaddr(uint32_t base, int row, int chunk) {
    return base + row * 128 + (((chunk) ^ (row & 7)) << 4);
}

// ---------------------------------------------------------------------------
// Kernel 0: split x and W into bf16 hi/lo pairs
// ---------------------------------------------------------------------------
__global__ __launch_bounds__(256) void split_kernel(const float* __restrict__ x,
                                                    const float* __restrict__ W)
{
    const size_t NX = (size_t)BB * NN * FIN;
    const size_t NW = (size_t)H * FOUT * FIN;
    size_t i = (size_t)blockIdx.x * 256 + threadIdx.x;
    size_t stride = (size_t)gridDim.x * 256;
    for (; i < NX + NW; i += stride) {
        if (i < NX) {
            float v = x[i];
            __nv_bfloat16 hi = __float2bfloat16_rn(v);
            __nv_bfloat16 lo = __float2bfloat16_rn(v - __bfloat162float(hi));
            g_xh[i] = hi; g_xl[i] = lo;
        } else {
            size_t j = i - NX;
            float v = W[j];
            __nv_bfloat16 hi = __float2bfloat16_rn(v);
            __nv_bfloat16 lo = __float2bfloat16_rn(v - __bfloat162float(hi));
            g_wh[j] = hi; g_wl[j] = lo;
        }
    }
}

// ---------------------------------------------------------------------------
// Kernel 1: h[hd] = x @ W[hd]^T via mma.sync bf16 split-3; store bf16 hi/lo
// ---------------------------------------------------------------------------
#define GA_H 0
#define GA_L 16384
#define GB_H 32768
#define GB_L 49152
#define G_TOTAL 65536

__global__ __launch_bounds__(256) void gemm_h_mma(void)
{
    extern __shared__ char sm[];
    const uint32_t sb = smem_u32(sm);
    const int tid = threadIdx.x;
    const int wid = tid >> 5;
    const int lane = tid & 31;
    const int m0 = blockIdx.x * 128;
    const int o0 = blockIdx.y * 128;
    const int hd = blockIdx.z;
    const int warp_m = (wid & 3) * 32;
    const int warp_n = (wid >> 2) * 64;

    float d[2][8][4];
#pragma unroll
    for (int i = 0; i < 2; i++)
#pragma unroll
        for (int j = 0; j < 8; j++)
#pragma unroll
            for (int c = 0; c < 4; c++) d[i][j][c] = 0.f;

    const char* xh = (const char*)g_xh + (size_t)m0 * FIN * 2;
    const char* xl = (const char*)g_xl + (size_t)m0 * FIN * 2;
    const char* wh = (const char*)g_wh + ((size_t)hd * FOUT + o0) * FIN * 2;
    const char* wl = (const char*)g_wl + ((size_t)hd * FOUT + o0) * FIN * 2;

    const int lt = lane >> 3;
    const int lr = lane & 7;

    for (int kc = 0; kc < FIN; kc += 64) {
        __syncthreads();
#pragma unroll
        for (int it = 0; it < 4; it++) {
            int idx = tid + it * 256;
            int r = idx >> 3, ch = idx & 7;
            size_t gb = ((size_t)r * FIN + kc) * 2 + ch * 16;
            uint32_t so = (uint32_t)(r * 128 + ((ch ^ (r & 7)) << 4));
            *(uint4*)(sm + GA_H + so) = *(const uint4*)(xh + gb);
            *(uint4*)(sm + GA_L + so) = *(const uint4*)(xl + gb);
            *(uint4*)(sm + GB_H + so) = *(const uint4*)(wh + gb);
            *(uint4*)(sm + GB_L + so) = *(const uint4*)(wl + gb);
        }
        __syncthreads();

#pragma unroll
        for (int kk = 0; kk < 64; kk += 16) {
            const int kch = kk >> 3;
            uint32_t ah[2][4], al[2][4];
#pragma unroll
            for (int mi = 0; mi < 2; mi++) {
                int row = warp_m + mi * 16 + (lt & 1) * 8 + lr;
                LDMX4(ah[mi][0], ah[mi][1], ah[mi][2], ah[mi][3],
                      lmaddr(sb + GA_H, row, kch + (lt >> 1)));
                LDMX4(al[mi][0], al[mi][1], al[mi][2], al[mi][3],
                      lmaddr(sb + GA_L, row, kch + (lt >> 1)));
            }
#pragma unroll
            for (int pr = 0; pr < 4; pr++) {
                int row = warp_n + pr * 16 + (lt & 1) * 8 + lr;
                uint32_t bh0, bh1, bh2, bh3, bl0, bl1, bl2, bl3;
                LDMX4(bh0, bh1, bh2, bh3, lmaddr(sb + GB_H, row, kch + (lt >> 1)));
                LDMX4(bl0, bl1, bl2, bl3, lmaddr(sb + GB_L, row, kch + (lt >> 1)));
#pragma unroll
                for (int mi = 0; mi < 2; mi++) {
                    MMA16816(d[mi][2 * pr],     ah[mi][0], ah[mi][1], ah[mi][2], ah[mi][3], bh0, bh2);
                    MMA16816(d[mi][2 * pr + 1], ah[mi][0], ah[mi][1], ah[mi][2], ah[mi][3], bh1, bh3);
                    MMA16816(d[mi][2 * pr],     ah[mi][0], ah[mi][1], ah[mi][2], ah[mi][3], bl0, bl2);
                    MMA16816(d[mi][2 * pr + 1], ah[mi][0], ah[mi][1], ah[mi][2], ah[mi][3], bl1, bl3);
                    MMA16816(d[mi][2 * pr],     al[mi][0], al[mi][1], al[mi][2], al[mi][3], bh0, bh2);
                    MMA16816(d[mi][2 * pr + 1], al[mi][0], al[mi][1], al[mi][2], al[mi][3], bh1, bh3);
                }
            }
        }
    }

    // epilogue: store bf16 hi/lo
    const int g = lane >> 2, t = lane & 3;
    const size_t hbase = (size_t)hd * BB * NN;
#pragma unroll
    for (int mi = 0; mi < 2; mi++) {
#pragma unroll
        for (int nj = 0; nj < 8; nj++) {
            int row = m0 + warp_m + mi * 16 + g;
            int col = o0 + warp_n + nj * 8 + 2 * t;
#pragma unroll
            for (int half = 0; half < 2; half++) {
                float v0 = d[mi][nj][half * 2], v1 = d[mi][nj][half * 2 + 1];
                __nv_bfloat16 h0 = __float2bfloat16_rn(v0);
                __nv_bfloat16 h1 = __float2bfloat16_rn(v1);
                __nv_bfloat16 l0 = __float2bfloat16_rn(v0 - __bfloat162float(h0));
                __nv_bfloat16 l1 = __float2bfloat16_rn(v1 - __bfloat162float(h1));
                size_t off = (hbase + row + half * 8) * FOUT + col;
                *(unsigned*)(g_hh + off) = (unsigned)__bfloat16_as_ushort(h0) |
                                           ((unsigned)__bfloat16_as_ushort(h1) << 16);
                *(unsigned*)(g_hl + off) = (unsigned)__bfloat16_as_ushort(l0) |
                                           ((unsigned)__bfloat16_as_ushort(l1) << 16);
            }
        }
    }
}

// ---------------------------------------------------------------------------
// Kernel 2: f1/f2 from hi+lo h (fp32-accurate), warp per row
// ---------------------------------------------------------------------------
__global__ __launch_bounds__(256) void f12_kernel(const float* __restrict__ a1,
                                                  const float* __restrict__ a2)
{
    int gw   = (blockIdx.x * 256 + threadIdx.x) >> 5;
    int lane = threadIdx.x & 31;
    int hd   = gw >> 13;
    const __nv_bfloat16* hh = g_hh + (size_t)gw * FOUT;
    const __nv_bfloat16* hl = g_hl + (size_t)gw * FOUT;
    const float* A1 = a1 + hd * FOUT;
    const float* A2 = a2 + hd * FOUT;
    float s1 = 0.f, s2 = 0.f;
#pragma unroll
    for (int i = 0; i < 8; i++) {
        int o = lane + i * 32;
        float hv = __bfloat162float(hh[o]) + __bfloat162float(hl[o]);
        s1 = fmaf(hv, A1[o], s1);
        s2 = fmaf(hv, A2[o], s2);
    }
#pragma unroll
    for (int off = 16; off; off >>= 1) {
        s1 += __shfl_xor_sync(0xffffffffu, s1, off);
        s2 += __shfl_xor_sync(0xffffffffu, s2, off);
    }
    if (lane == 0) { g_f1[gw] = s1; g_f2[gw] = s2; }
}

// ---------------------------------------------------------------------------
// Kernel 3: attn via mma.sync: out-tile 64x256, K=1024 in 64-chunks,
// p generated in-kernel (bf16), h hi streamed via cp.async double-buffer.
// 512 threads = 16 warps (4m x 4n), elu-sum over heads + fused log_softmax.
// ---------------------------------------------------------------------------
#define AS_HB0  0
#define AS_HB1  32768
#define AS_PB0  65536
#define AS_PB1  73728
#define AS_F2   81920
#define AS_MSK  86016
#define AS_F1   94208
#define AS_RED  94464
#define AS_RED2 95488
#define AS_INV  96512
#define AS_ROWM 96768
#define AS_LSE  97024
#define AS_TOTAL 97280

__global__ __launch_bounds__(512, 1) void attn_mma(const int* __restrict__ adj,
                                                   float* __restrict__ out)
{
    extern __shared__ char sm[];
    const uint32_t sb = smem_u32(sm);
    float*    f2_s  = (float*)(sm + AS_F2);
    float*    f1_s  = (float*)(sm + AS_F1);
    unsigned* mskw  = (unsigned*)(sm + AS_MSK);
    float*    red   = (float*)(sm + AS_RED);
    float*    red2  = (float*)(sm + AS_RED2);
    float*    inv_s = (float*)(sm + AS_INV);
    float*    rowm  = (float*)(sm + AS_ROWM);
    float*    lse   = (float*)(sm + AS_LSE);

    const int tid  = threadIdx.x;
    const int lane = tid & 31;
    const int wid  = tid >> 5;
    const int wm   = wid & 3;         // warp m-tile (16 rows)
    const int wn   = wid >> 2;        // warp n-tile (64 cols)
    const int b    = blockIdx.y;
    const int n0   = blockIdx.x * 64;

    // pgen mapping
    const int prow8 = tid >> 3;       // 0..63
    const int k8    = tid & 7;        // 8-col group

    // build mask bits: mskw[row][0..31]
    for (int pass = 0; pass < 128; pass++) {
        int row = pass >> 1;
        int m = ((pass & 1) << 9) + tid;   // tid<512 -> m covers 0..1023 over 2 passes
        int a = adj[((size_t)b * NN + n0 + row) * NN + m];
        unsigned w = __ballot_sync(0xffffffffu, a == 0);
        if (lane == 0) mskw[row * 32 + (m >> 5)] = w;
    }

    float tot[8][4];
#pragma unroll
    for (int j = 0; j < 8; j++)
#pragma unroll
        for (int c = 0; c < 4; c++) tot[j][c] = 0.f;

    const int g = lane >> 2, t4 = lane & 3;
    const int r0 = wm * 16 + g, r1 = r0 + 8;

    for (int hd = 0; hd < H; hd++) {
        const int base = (hd * BB + b) * NN;
        const __nv_bfloat16* hsrc = g_hh + (size_t)base * FOUT;

        __syncthreads();   // prior head done with F2/RED/INV
        // stage f1/f2
        f2_s[tid] = g_f2[base + tid];
        f2_s[tid + 512] = g_f2[base + tid + 512];
        if (tid < 64) f1_s[tid] = g_f1[base + n0 + tid];

        // prologue: cp.async h chunk 0 -> HB0
#pragma unroll
        for (int i = 0; i < 4; i++) {
            int idx = tid + 512 * i;
            int r = idx >> 5, cc = idx & 31;
            uint32_t dst = sb + AS_HB0 + r * 512 + ((cc ^ (r & 7)) << 4);
            CPA16(dst, (const char*)(hsrc + (size_t)r * FOUT) + cc * 16);
        }
        CP_COMMIT();
        __syncthreads();   // f1/f2/mask visible

        float d[8][4];
#pragma unroll
        for (int j = 0; j < 8; j++)
#pragma unroll
            for (int c = 0; c < 4; c++) d[j][c] = 0.f;
        float psum = 0.f;
        const float f1v = f1_s[prow8];

        for (int ck = 0; ck < 16; ck++) {
            const int kc = ck * 64;
            // issue next h chunk
            if (ck < 15) {
                const __nv_bfloat16* hnext = hsrc + (size_t)(kc + 64) * FOUT;
                uint32_t hb_next = sb + ((ck & 1) ? AS_HB0 : AS_HB1);
#pragma unroll
                for (int i = 0; i < 4; i++) {
                    int idx = tid + 512 * i;
                    int r = idx >> 5, cc = idx & 31;
                    uint32_t dst = hb_next + r * 512 + ((cc ^ (r & 7)) << 4);
                    CPA16(dst, (const char*)(hnext + (size_t)r * FOUT) + cc * 16);
                }
                CP_COMMIT();
            }

            // pgen: 8 values for (row=prow8, cols kc + k8*8 .. +7)
            {
                unsigned word = mskw[prow8 * 32 + (ck << 1) + (k8 >> 2)];
                unsigned byte = (word >> ((k8 & 3) << 3)) & 0xffu;
                const float4 fa = *(const float4*)(f2_s + kc + k8 * 8);
                const float4 fb = *(const float4*)(f2_s + kc + k8 * 8 + 4);
                float pv[8];
                const float f2v[8] = {fa.x, fa.y, fa.z, fa.w, fb.x, fb.y, fb.z, fb.w};
#pragma unroll
                for (int j = 0; j < 8; j++) {
                    float e = f1v + f2v[j];
                    e = (e > 0.f) ? e : ALPHA * e;
                    float p = ((byte >> j) & 1u) ? 0.f : __expf(e);
                    pv[j] = p;
                    psum += p;
                }
                unsigned q[4];
#pragma unroll
                for (int j = 0; j < 4; j++)
                    q[j] = (unsigned)__bfloat16_as_ushort(__float2bfloat16_rn(pv[2 * j])) |
                           ((unsigned)__bfloat16_as_ushort(__float2bfloat16_rn(pv[2 * j + 1])) << 16);
                uint32_t pb = (ck & 1) ? AS_PB1 : AS_PB0;
                *(uint4*)(sm + pb + prow8 * 128 + ((k8 ^ (prow8 & 7)) << 4)) =
                    make_uint4(q[0], q[1], q[2], q[3]);
            }

            if (ck < 15) { CP_WAIT1(); } else { CP_WAIT0(); }
            __syncthreads();   // p + h chunk ready

            // MMA over this chunk
            const uint32_t pbb = sb + ((ck & 1) ? AS_PB1 : AS_PB0);
            const uint32_t hbb = sb + ((ck & 1) ? AS_HB1 : AS_HB0);
#pragma unroll
            for (int ks = 0; ks < 64; ks += 16) {
                int prow = wm * 16 + (lane & 7) + ((lane >> 3) & 1) * 8;
                int pch = (ks >> 3) + (lane >> 4);
                uint32_t a0, a1, a2, a3;
                LDMX4(a0, a1, a2, a3, pbb + prow * 128 + ((pch ^ (prow & 7)) << 4));
                int hrow = ks + (lane & 7) + ((lane >> 3) & 1) * 8;
#pragma unroll
                for (int nt = 0; nt < 4; nt++) {
                    int hch = (wn << 3) + (nt << 1) + (lane >> 4);
                    uint32_t b0, b1, b2, b3;
                    LDMX4T(b0, b1, b2, b3, hbb + hrow * 512 + ((hch ^ (hrow & 7)) << 4));
                    MMA16816(d[2 * nt],     a0, a1, a2, a3, b0, b1);
                    MMA16816(d[2 * nt + 1], a0, a1, a2, a3, b2, b3);
                }
            }
            __syncthreads();   // all warps done before next pgen/cp.async overwrites
        }

        // rowsum reduce -> inv
        red[prow8 * 8 + k8] = psum;
        __syncthreads();
        if (tid < 64) {
            float s = 0.f;
#pragma unroll
            for (int j = 0; j < 8; j++) s += red[tid * 8 + j];
            inv_s[tid] = 1.f / s;
        }
        __syncthreads();

        const float i0 = inv_s[r0], i1 = inv_s[r1];
#pragma unroll
        for (int j = 0; j < 8; j++) {
            float v0 = d[j][0] * i0, v1 = d[j][1] * i0;
            float v2 = d[j][2] * i1, v3 = d[j][3] * i1;
            tot[j][0] += (v0 > 0.f) ? v0 : (__expf(v0) - 1.f);
            tot[j][1] += (v1 > 0.f) ? v1 : (__expf(v1) - 1.f);
            tot[j][2] += (v2 > 0.f) ? v2 : (__expf(v2) - 1.f);
            tot[j][3] += (v3 > 0.f) ? v3 : (__expf(v3) - 1.f);
        }
    }

    // ---- fused log_softmax over o (256 cols) for 64 rows ----
    __syncthreads();
    float vm0 = -3.0e38f, vm1 = -3.0e38f;
#pragma unroll
    for (int j = 0; j < 8; j++) {
        vm0 = fmaxf(vm0, fmaxf(tot[j][0], tot[j][1]));
        vm1 = fmaxf(vm1, fmaxf(tot[j][2], tot[j][3]));
    }
    vm0 = fmaxf(vm0, __shfl_xor_sync(0xffffffffu, vm0, 1));
    vm0 = fmaxf(vm0, __shfl_xor_sync(0xffffffffu, vm0, 2));
    vm1 = fmaxf(vm1, __shfl_xor_sync(0xffffffffu, vm1, 1));
    vm1 = fmaxf(vm1, __shfl_xor_sync(0xffffffffu, vm1, 2));
    if (t4 == 0) { red[r0 * 4 + wn] = vm0; red[r1 * 4 + wn] = vm1; }
    __syncthreads();
    if (tid < 64) {
        float v = red[tid * 4];
#pragma unroll
        for (int j = 1; j < 4; j++) v = fmaxf(v, red[tid * 4 + j]);
        rowm[tid] = v;
    }
    __syncthreads();
    const float rm0 = rowm[r0], rm1 = rowm[r1];
    float s0 = 0.f, s1 = 0.f;
#pragma unroll
    for (int j = 0; j < 8; j++) {
        s0 += __expf(tot[j][0] - rm0) + __expf(tot[j][1] - rm0);
        s1 += __expf(tot[j][2] - rm1) + __expf(tot[j][3] - rm1);
    }
    s0 += __shfl_xor_sync(0xffffffffu, s0, 1);
    s0 += __shfl_xor_sync(0xffffffffu, s0, 2);
    s1 += __shfl_xor_sync(0xffffffffu, s1, 1);
    s1 += __shfl_xor_sync(0xffffffffu, s1, 2);
    if (t4 == 0) { red2[r0 * 4 + wn] = s0; red2[r1 * 4 + wn] = s1; }
    __syncthreads();
    if (tid < 64) {
        float v = 0.f;
#pragma unroll
        for (int j = 0; j < 4; j++) v += red2[tid * 4 + j];
        lse[tid] = logf(v);
    }
    __syncthreads();
    const float c0 = rm0 + lse[r0], c1 = rm1 + lse[r1];
    float* o0p = out + ((size_t)b * NN + n0 + r0) * FOUT;
    float* o1p = out + ((size_t)b * NN + n0 + r1) * FOUT;
#pragma unroll
    for (int j = 0; j < 8; j++) {
        int col = wn * 64 + j * 8 + 2 * t4;
        *(float2*)(o0p + col) = make_float2(tot[j][0] - c0, tot[j][1] - c0);
        *(float2*)(o1p + col) = make_float2(tot[j][2] - c1, tot[j][3] - c1);
    }
}

// ---------------------------------------------------------------------------
extern "C" void kernel_launch(void* const* d_in, const int* in_sizes, int n_in,
                              void* d_out, int out_size)
{
    const float* x   = (const float*)d_in[0];
    const int*   adj = (const int*)d_in[1];
    const float* W   = (const float*)d_in[2];
    const float* a1  = (const float*)d_in[3];
    const float* a2  = (const float*)d_in[4];
    float* out = (float*)d_out;

    (void)in_sizes; (void)n_in; (void)out_size;

    cudaFuncSetAttribute(gemm_h_mma, cudaFuncAttributeMaxDynamicSharedMemorySize, G_TOTAL);
    cudaFuncSetAttribute(attn_mma, cudaFuncAttributeMaxDynamicSharedMemorySize, AS_TOTAL);

    split_kernel<<<2560, 256>>>(x, W);
    gemm_h_mma<<<dim3(64, 2, 8), 256, G_TOTAL>>>();
    f12_kernel<<<8192, 256>>>(a1, a2);
    attn_mma<<<dim3(16, 8), 512, AS_TOTAL>>>(adj, out);
}

// round 13
// speedup vs baseline: 5.6440x; 1.0800x over previous
#include <cuda_runtime.h>
#include <cuda_bf16.h>
#include <math.h>
#include <cstdint>

#define H    8
#define BB   8
#define NN   1024
#define FIN  512
#define FOUT 256
#define ALPHA 0.2f

// Scratch (device globals per harness allocation rules)
__device__ float g_f1[H * BB * NN];
__device__ float g_f2[H * BB * NN];
__device__ float g_c1[H * FIN];
__device__ float g_c2[H * FIN];
__device__ __nv_bfloat16 g_xh[(size_t)BB * NN * FIN];
__device__ __nv_bfloat16 g_wh[(size_t)H * FOUT * FIN];
__device__ __nv_bfloat16 g_wl[(size_t)H * FOUT * FIN];
__device__ __nv_bfloat16 g_hh[(size_t)H * BB * NN * FOUT];   // h bf16 hi

// ---- ldmatrix / mma.sync helpers (sm_80-era PTX, valid on plain sm_103) ---
__device__ __forceinline__ uint32_t smem_u32(const void* p) {
    uint32_t a;
    asm("{ .reg .u64 t; cvta.to.shared.u64 t, %1; cvt.u32.u64 %0, t; }" : "=r"(a) : "l"(p));
    return a;
}
#define LDMX4(r0, r1, r2, r3, a) \
    asm volatile("ldmatrix.sync.aligned.m8n8.x4.shared.b16 {%0,%1,%2,%3}, [%4];" \
                 : "=r"(r0), "=r"(r1), "=r"(r2), "=r"(r3) : "r"(a))
#define LDMX4T(r0, r1, r2, r3, a) \
    asm volatile("ldmatrix.sync.aligned.m8n8.x4.trans.shared.b16 {%0,%1,%2,%3}, [%4];" \
                 : "=r"(r0), "=r"(r1), "=r"(r2), "=r"(r3) : "r"(a))
#define MMA16816(d, a0, a1, a2, a3, b0, b1) \
    asm volatile("mma.sync.aligned.m16n8k16.row.col.f32.bf16.bf16.f32 " \
                 "{%0,%1,%2,%3},{%4,%5,%6,%7},{%8,%9},{%0,%1,%2,%3};" \
                 : "+f"((d)[0]), "+f"((d)[1]), "+f"((d)[2]), "+f"((d)[3]) \
                 : "r"(a0), "r"(a1), "r"(a2), "r"(a3), "r"(b0), "r"(b1))
#define CPA16(dst, src) \
    asm volatile("cp.async.cg.shared.global [%0], [%1], 16;" :: "r"(dst), "l"(src) : "memory")
#define CP_COMMIT() asm volatile("cp.async.commit_group;" ::: "memory")
#define CP_WAIT0()  asm volatile("cp.async.wait_group 0;" ::: "memory")
#define CP_WAIT1()  asm volatile("cp.async.wait_group 1;" ::: "memory")
// cvt d, a, b -> d.hi = a, d.lo = b
#define CVT_BF2(q, hi, lo) \
    asm("cvt.rn.bf16x2.f32 %0, %1, %2;" : "=r"(q) : "f"(hi), "f"(lo))

__device__ __forceinline__ uint32_t lmaddr(uint32_t base, int row, int chunk) {
    return base + row * 128 + (((chunk) ^ (row & 7)) << 4);
}

// ---------------------------------------------------------------------------
// Kernel 0: split x (hi only) and W (hi/lo) into bf16
// ---------------------------------------------------------------------------
__global__ __launch_bounds__(256) void split_kernel(const float* __restrict__ x,
                                                    const float* __restrict__ W)
{
    const size_t NX = (size_t)BB * NN * FIN;
    const size_t NW = (size_t)H * FOUT * FIN;
    size_t i = (size_t)blockIdx.x * 256 + threadIdx.x;
    size_t stride = (size_t)gridDim.x * 256;
    for (; i < NX + NW; i += stride) {
        if (i < NX) {
            g_xh[i] = __float2bfloat16_rn(x[i]);
        } else {
            size_t j = i - NX;
            float v = W[j];
            __nv_bfloat16 hi = __float2bfloat16_rn(v);
            __nv_bfloat16 lo = __float2bfloat16_rn(v - __bfloat162float(hi));
            g_wh[j] = hi; g_wl[j] = lo;
        }
    }
}

// ---------------------------------------------------------------------------
// Kernel 0b: c1/c2[hd][f] = sum_o W[hd][o][f] * a{1,2}[hd][o]
// ---------------------------------------------------------------------------
__global__ __launch_bounds__(512) void c12_kernel(const float* __restrict__ W,
                                                  const float* __restrict__ a1,
                                                  const float* __restrict__ a2)
{
    __shared__ float a1s[FOUT], a2s[FOUT];
    const int hd = blockIdx.x;
    const int f = threadIdx.x;
    for (int i = threadIdx.x; i < FOUT; i += 512) {
        a1s[i] = a1[hd * FOUT + i];
        a2s[i] = a2[hd * FOUT + i];
    }
    __syncthreads();
    const float* Wp = W + (size_t)hd * FOUT * FIN + f;
    float s1 = 0.f, s2 = 0.f;
#pragma unroll 4
    for (int o = 0; o < FOUT; o++) {
        float w = Wp[(size_t)o * FIN];
        s1 = fmaf(w, a1s[o], s1);
        s2 = fmaf(w, a2s[o], s2);
    }
    g_c1[hd * FIN + f] = s1;
    g_c2[hd * FIN + f] = s2;
}

// ---------------------------------------------------------------------------
// Kernel 0c: f1/f2[hd][r] = x[r] . c{1,2}[hd]  (warp per row, all heads)
// ---------------------------------------------------------------------------
__global__ __launch_bounds__(256) void f12x_kernel(const float* __restrict__ x)
{
    __shared__ float cs[2 * H * FIN];   // 32 KB
    for (int i = threadIdx.x; i < H * FIN; i += 256) {
        cs[i] = g_c1[i];
        cs[H * FIN + i] = g_c2[i];
    }
    __syncthreads();
    const int w = threadIdx.x >> 5, lane = threadIdx.x & 31;
    const int r = blockIdx.x * 8 + w;
    const float* xp = x + (size_t)r * FIN;
    float acc1[8], acc2[8];
#pragma unroll
    for (int hd = 0; hd < 8; hd++) { acc1[hd] = 0.f; acc2[hd] = 0.f; }
#pragma unroll
    for (int i = 0; i < 4; i++) {
        const int off = lane * 4 + i * 128;
        float4 xv = *(const float4*)(xp + off);
#pragma unroll
        for (int hd = 0; hd < 8; hd++) {
            float4 cv = *(const float4*)(cs + hd * FIN + off);
            acc1[hd] = fmaf(xv.x, cv.x, fmaf(xv.y, cv.y, fmaf(xv.z, cv.z, fmaf(xv.w, cv.w, acc1[hd]))));
            float4 dv = *(const float4*)(cs + H * FIN + hd * FIN + off);
            acc2[hd] = fmaf(xv.x, dv.x, fmaf(xv.y, dv.y, fmaf(xv.z, dv.z, fmaf(xv.w, dv.w, acc2[hd]))));
        }
    }
#pragma unroll
    for (int hd = 0; hd < 8; hd++) {
#pragma unroll
        for (int off = 16; off; off >>= 1) {
            acc1[hd] += __shfl_xor_sync(0xffffffffu, acc1[hd], off);
            acc2[hd] += __shfl_xor_sync(0xffffffffu, acc2[hd], off);
        }
    }
    if (lane == 0) {
#pragma unroll
        for (int hd = 0; hd < 8; hd++) {
            g_f1[hd * (BB * NN) + r] = acc1[hd];
            g_f2[hd * (BB * NN) + r] = acc2[hd];
        }
    }
}

// ---------------------------------------------------------------------------
// Kernel 1: h[hd] = xh @ (Wh + Wl)^T via mma.sync (2 terms); store bf16 hi
// ---------------------------------------------------------------------------
#define GA_H 0
#define GB_H 16384
#define GB_L 32768
#define G_TOTAL 49152

__global__ __launch_bounds__(256) void gemm_h_mma(void)
{
    extern __shared__ char sm[];
    const uint32_t sb = smem_u32(sm);
    const int tid = threadIdx.x;
    const int wid = tid >> 5;
    const int lane = tid & 31;
    const int m0 = blockIdx.x * 128;
    const int o0 = blockIdx.y * 128;
    const int hd = blockIdx.z;
    const int warp_m = (wid & 3) * 32;
    const int warp_n = (wid >> 2) * 64;

    float d[2][8][4];
#pragma unroll
    for (int i = 0; i < 2; i++)
#pragma unroll
        for (int j = 0; j < 8; j++)
#pragma unroll
            for (int c = 0; c < 4; c++) d[i][j][c] = 0.f;

    const char* xh = (const char*)g_xh + (size_t)m0 * FIN * 2;
    const char* wh = (const char*)g_wh + ((size_t)hd * FOUT + o0) * FIN * 2;
    const char* wl = (const char*)g_wl + ((size_t)hd * FOUT + o0) * FIN * 2;

    const int lt = lane >> 3;
    const int lr = lane & 7;

    for (int kc = 0; kc < FIN; kc += 64) {
        __syncthreads();
#pragma unroll
        for (int it = 0; it < 4; it++) {
            int idx = tid + it * 256;
            int r = idx >> 3, ch = idx & 7;
            size_t gb = ((size_t)r * FIN + kc) * 2 + ch * 16;
            uint32_t so = (uint32_t)(r * 128 + ((ch ^ (r & 7)) << 4));
            *(uint4*)(sm + GA_H + so) = *(const uint4*)(xh + gb);
            *(uint4*)(sm + GB_H + so) = *(const uint4*)(wh + gb);
            *(uint4*)(sm + GB_L + so) = *(const uint4*)(wl + gb);
        }
        __syncthreads();

#pragma unroll
        for (int kk = 0; kk < 64; kk += 16) {
            const int kch = kk >> 3;
            uint32_t ah[2][4];
#pragma unroll
            for (int mi = 0; mi < 2; mi++) {
                int row = warp_m + mi * 16 + (lt & 1) * 8 + lr;
                LDMX4(ah[mi][0], ah[mi][1], ah[mi][2], ah[mi][3],
                      lmaddr(sb + GA_H, row, kch + (lt >> 1)));
            }
#pragma unroll
            for (int pr = 0; pr < 4; pr++) {
                int row = warp_n + pr * 16 + (lt & 1) * 8 + lr;
                uint32_t bh0, bh1, bh2, bh3, bl0, bl1, bl2, bl3;
                LDMX4(bh0, bh1, bh2, bh3, lmaddr(sb + GB_H, row, kch + (lt >> 1)));
                LDMX4(bl0, bl1, bl2, bl3, lmaddr(sb + GB_L, row, kch + (lt >> 1)));
#pragma unroll
                for (int mi = 0; mi < 2; mi++) {
                    MMA16816(d[mi][2 * pr],     ah[mi][0], ah[mi][1], ah[mi][2], ah[mi][3], bh0, bh2);
                    MMA16816(d[mi][2 * pr + 1], ah[mi][0], ah[mi][1], ah[mi][2], ah[mi][3], bh1, bh3);
                    MMA16816(d[mi][2 * pr],     ah[mi][0], ah[mi][1], ah[mi][2], ah[mi][3], bl0, bl2);
                    MMA16816(d[mi][2 * pr + 1], ah[mi][0], ah[mi][1], ah[mi][2], ah[mi][3], bl1, bl3);
                }
            }
        }
    }

    // epilogue: store bf16 hi only
    const int g = lane >> 2, t = lane & 3;
    const size_t hbase = (size_t)hd * BB * NN;
#pragma unroll
    for (int mi = 0; mi < 2; mi++) {
#pragma unroll
        for (int nj = 0; nj < 8; nj++) {
            int row = m0 + warp_m + mi * 16 + g;
            int col = o0 + warp_n + nj * 8 + 2 * t;
#pragma unroll
            for (int half = 0; half < 2; half++) {
                unsigned q;
                CVT_BF2(q, d[mi][nj][half * 2 + 1], d[mi][nj][half * 2]);
                size_t off = (hbase + row + half * 8) * FOUT + col;
                *(unsigned*)(g_hh + off) = q;
            }
        }
    }
}

// ---------------------------------------------------------------------------
// Kernel 3: attn via mma.sync, triple-buffered (one barrier per k-chunk)
// out-tile 64x256 per CTA, K=1024 in 64-chunks, 512 threads = 16 warps.
// ---------------------------------------------------------------------------
#define AS_HB0  0
#define AS_HB1  32768
#define AS_HB2  65536
#define AS_PB0  98304
#define AS_PB1  106496
#define AS_PB2  114688
#define AS_F2   122880
#define AS_MSK  126976
#define AS_F1   135168
#define AS_RED  135424
#define AS_RED2 137472
#define AS_INV  138496
#define AS_ROWM 138752
#define AS_LSE  139008
#define AS_TOTAL 139264

__global__ __launch_bounds__(512, 1) void attn_mma(const int* __restrict__ adj,
                                                   float* __restrict__ out)
{
    extern __shared__ char sm[];
    const uint32_t sb = smem_u32(sm);
    float*    f2_s  = (float*)(sm + AS_F2);
    float*    f1_s  = (float*)(sm + AS_F1);
    unsigned* mskw  = (unsigned*)(sm + AS_MSK);
    float*    red   = (float*)(sm + AS_RED);
    float*    red2  = (float*)(sm + AS_RED2);
    float*    inv_s = (float*)(sm + AS_INV);
    float*    rowm  = (float*)(sm + AS_ROWM);
    float*    lse   = (float*)(sm + AS_LSE);

    const int tid  = threadIdx.x;
    const int lane = tid & 31;
    const int wid  = tid >> 5;
    const int wm   = wid & 3;
    const int wn   = wid >> 2;
    const int b    = blockIdx.y;
    const int n0   = blockIdx.x * 64;

    const int prow8 = tid >> 3;       // 0..63
    const int k8    = tid & 7;

    // mask bits
    for (int pass = 0; pass < 128; pass++) {
        int row = pass >> 1;
        int m = ((pass & 1) << 9) + tid;
        int a = adj[((size_t)b * NN + n0 + row) * NN + m];
        unsigned w = __ballot_sync(0xffffffffu, a == 0);
        if (lane == 0) mskw[row * 32 + (m >> 5)] = w;
    }

    float tot[8][4];
#pragma unroll
    for (int j = 0; j < 8; j++)
#pragma unroll
        for (int c = 0; c < 4; c++) tot[j][c] = 0.f;

    const int g = lane >> 2, t4 = lane & 3;
    const int r0 = wm * 16 + g, r1 = r0 + 8;

    float psum = 0.f;

    auto cp_h = [&](const __nv_bfloat16* hsrc, int ck, int hOff) {
#pragma unroll
        for (int i = 0; i < 4; i++) {
            int idx = tid + 512 * i;
            int r = idx >> 5, cc = idx & 31;
            uint32_t dst = sb + hOff + r * 512 + ((cc ^ (r & 7)) << 4);
            CPA16(dst, (const char*)(hsrc + (size_t)(ck * 64 + r) * FOUT) + cc * 16);
        }
    };
    auto pgen = [&](int ck, int pOff, float f1v) {
        unsigned word = mskw[prow8 * 32 + (ck << 1) + (k8 >> 2)];
        unsigned byte = (word >> ((k8 & 3) << 3)) & 0xffu;
        const int kc = ck * 64;
        const float4 fa = *(const float4*)(f2_s + kc + k8 * 8);
        const float4 fb = *(const float4*)(f2_s + kc + k8 * 8 + 4);
        const float f2v[8] = {fa.x, fa.y, fa.z, fa.w, fb.x, fb.y, fb.z, fb.w};
        float pv[8];
#pragma unroll
        for (int j = 0; j < 8; j++) {
            float e = f1v + f2v[j];
            e = (e > 0.f) ? e : ALPHA * e;
            float p = ((byte >> j) & 1u) ? 0.f : __expf(e);
            pv[j] = p;
            psum += p;
        }
        uint4 q;
        CVT_BF2(q.x, pv[1], pv[0]);
        CVT_BF2(q.y, pv[3], pv[2]);
        CVT_BF2(q.z, pv[5], pv[4]);
        CVT_BF2(q.w, pv[7], pv[6]);
        *(uint4*)(sm + pOff + prow8 * 128 + ((k8 ^ (prow8 & 7)) << 4)) = q;
    };

    for (int hd = 0; hd < H; hd++) {
        const int base = (hd * BB + b) * NN;
        const __nv_bfloat16* hsrc = g_hh + (size_t)base * FOUT;

        __syncthreads();            // all warps finished previous head entirely
        f2_s[tid] = g_f2[base + tid];
        f2_s[tid + 512] = g_f2[base + tid + 512];
        if (tid < 64) f1_s[tid] = g_f1[base + n0 + tid];

        int hOffA = AS_HB0, hOffB = AS_HB1, hOffC = AS_HB2;
        int pOffA = AS_PB0, pOffB = AS_PB1, pOffC = AS_PB2;

        cp_h(hsrc, 0, hOffA); CP_COMMIT();
        __syncthreads();            // f1/f2 visible
        psum = 0.f;
        const float f1v = f1_s[prow8];
        pgen(0, pOffA, f1v);
        cp_h(hsrc, 1, hOffB); CP_COMMIT();

        float d[8][4];
#pragma unroll
        for (int j = 0; j < 8; j++)
#pragma unroll
            for (int c = 0; c < 4; c++) d[j][c] = 0.f;

        // Hazard audit (skew <= 1 iter, single barrier per iter, mod-3 bufs):
        //   pgen(ck+1) writes P[(ck+1)%3]; concurrent readers: MMA(ck) P[ck%3],
        //   lagging MMA(ck-1) P[(ck-1)%3] -> all distinct mod 3. Same for
        //   cp(ck+2) writing H[(ck+2)%3] vs MMA(ck)/MMA(ck-1) reads.
        for (int ck = 0; ck < 16; ck++) {
            if (ck == 15) { CP_WAIT0(); } else { CP_WAIT1(); }
            __syncthreads();        // p(ck) + h(ck) ready everywhere
            if (ck + 2 < 16) { cp_h(hsrc, ck + 2, hOffC); CP_COMMIT(); }
            if (ck + 1 < 16) pgen(ck + 1, pOffB, f1v);

            const uint32_t pbb = sb + pOffA;
            const uint32_t hbb = sb + hOffA;
#pragma unroll
            for (int ks = 0; ks < 64; ks += 16) {
                int prow = wm * 16 + (lane & 7) + ((lane >> 3) & 1) * 8;
                int pch = (ks >> 3) + (lane >> 4);
                uint32_t a0, a1, a2, a3;
                LDMX4(a0, a1, a2, a3, pbb + prow * 128 + ((pch ^ (prow & 7)) << 4));
                int hrow = ks + (lane & 7) + ((lane >> 3) & 1) * 8;
#pragma unroll
                for (int nt = 0; nt < 4; nt++) {
                    int hch = (wn << 3) + (nt << 1) + (lane >> 4);
                    uint32_t b0, b1, b2, b3;
                    LDMX4T(b0, b1, b2, b3, hbb + hrow * 512 + ((hch ^ (hrow & 7)) << 4));
                    MMA16816(d[2 * nt],     a0, a1, a2, a3, b0, b1);
                    MMA16816(d[2 * nt + 1], a0, a1, a2, a3, b2, b3);
                }
            }
            int t = hOffA; hOffA = hOffB; hOffB = hOffC; hOffC = t;
            t = pOffA; pOffA = pOffB; pOffB = pOffC; pOffC = t;
        }

        red[prow8 * 8 + k8] = psum;
        __syncthreads();
        if (tid < 64) {
            float s = 0.f;
#pragma unroll
            for (int j = 0; j < 8; j++) s += red[tid * 8 + j];
            inv_s[tid] = 1.f / s;
        }
        __syncthreads();

        const float i0 = inv_s[r0], i1 = inv_s[r1];
#pragma unroll
        for (int j = 0; j < 8; j++) {
            float v0 = d[j][0] * i0, v1 = d[j][1] * i0;
            float v2 = d[j][2] * i1, v3 = d[j][3] * i1;
            tot[j][0] += (v0 > 0.f) ? v0 : (__expf(v0) - 1.f);
            tot[j][1] += (v1 > 0.f) ? v1 : (__expf(v1) - 1.f);
            tot[j][2] += (v2 > 0.f) ? v2 : (__expf(v2) - 1.f);
            tot[j][3] += (v3 > 0.f) ? v3 : (__expf(v3) - 1.f);
        }
    }

    // ---- fused log_softmax over o (256 cols) for 64 rows ----
    __syncthreads();
    float vm0 = -3.0e38f, vm1 = -3.0e38f;
#pragma unroll
    for (int j = 0; j < 8; j++) {
        vm0 = fmaxf(vm0, fmaxf(tot[j][0], tot[j][1]));
        vm1 = fmaxf(vm1, fmaxf(tot[j][2], tot[j][3]));
    }
    vm0 = fmaxf(vm0, __shfl_xor_sync(0xffffffffu, vm0, 1));
    vm0 = fmaxf(vm0, __shfl_xor_sync(0xffffffffu, vm0, 2));
    vm1 = fmaxf(vm1, __shfl_xor_sync(0xffffffffu, vm1, 1));
    vm1 = fmaxf(vm1, __shfl_xor_sync(0xffffffffu, vm1, 2));
    if (t4 == 0) { red[r0 * 4 + wn] = vm0; red[r1 * 4 + wn] = vm1; }
    __syncthreads();
    if (tid < 64) {
        float v = red[tid * 4];
#pragma unroll
        for (int j = 1; j < 4; j++) v = fmaxf(v, red[tid * 4 + j]);
        rowm[tid] = v;
    }
    __syncthreads();
    const float rm0 = rowm[r0], rm1 = rowm[r1];
    float s0 = 0.f, s1 = 0.f;
#pragma unroll
    for (int j = 0; j < 8; j++) {
        s0 += __expf(tot[j][0] - rm0) + __expf(tot[j][1] - rm0);
        s1 += __expf(tot[j][2] - rm1) + __expf(tot[j][3] - rm1);
    }
    s0 += __shfl_xor_sync(0xffffffffu, s0, 1);
    s0 += __shfl_xor_sync(0xffffffffu, s0, 2);
    s1 += __shfl_xor_sync(0xffffffffu, s1, 1);
    s1 += __shfl_xor_sync(0xffffffffu, s1, 2);
    if (t4 == 0) { red2[r0 * 4 + wn] = s0; red2[r1 * 4 + wn] = s1; }
    __syncthreads();
    if (tid < 64) {
        float v = 0.f;
#pragma unroll
        for (int j = 0; j < 4; j++) v += red2[tid * 4 + j];
        lse[tid] = logf(v);
    }
    __syncthreads();
    const float c0 = rm0 + lse[r0], c1 = rm1 + lse[r1];
    float* o0p = out + ((size_t)b * NN + n0 + r0) * FOUT;
    float* o1p = out + ((size_t)b * NN + n0 + r1) * FOUT;
#pragma unroll
    for (int j = 0; j < 8; j++) {
        int col = wn * 64 + j * 8 + 2 * t4;
        *(float2*)(o0p + col) = make_float2(tot[j][0] - c0, tot[j][1] - c0);
        *(float2*)(o1p + col) = make_float2(tot[j][2] - c1, tot[j][3] - c1);
    }
}

// ---------------------------------------------------------------------------
extern "C" void kernel_launch(void* const* d_in, const int* in_sizes, int n_in,
                              void* d_out, int out_size)
{
    const float* x   = (const float*)d_in[0];
    const int*   adj = (const int*)d_in[1];
    const float* W   = (const float*)d_in[2];
    const float* a1  = (const float*)d_in[3];
    const float* a2  = (const float*)d_in[4];
    float* out = (float*)d_out;

    (void)in_sizes; (void)n_in; (void)out_size;

    cudaFuncSetAttribute(gemm_h_mma, cudaFuncAttributeMaxDynamicSharedMemorySize, G_TOTAL);
    cudaFuncSetAttribute(attn_mma, cudaFuncAttributeMaxDynamicSharedMemorySize, AS_TOTAL);

    split_kernel<<<2560, 256>>>(x, W);
    c12_kernel<<<8, 512>>>(W, a1, a2);
    f12x_kernel<<<1024, 256>>>(x);
    gemm_h_mma<<<dim3(64, 2, 8), 256, G_TOTAL>>>();
    attn_mma<<<dim3(16, 8), 512, AS_TOTAL>>>(adj, out);
}

// round 15
// speedup vs baseline: 7.2991x; 1.2933x over previous
#include <cuda_runtime.h>
#include <cuda_bf16.h>
#include <math.h>
#include <cstdint>

#define H    8
#define BB   8
#define NN   1024
#define FIN  512
#define FOUT 256
#define ALPHA 0.2f

// Scratch (device globals per harness allocation rules)
__device__ float g_f1[H * BB * NN];
__device__ float g_f2[H * BB * NN];
__device__ float g_c1[H * FIN];
__device__ float g_c2[H * FIN];
__device__ __nv_bfloat16 g_xh[(size_t)BB * NN * FIN];
__device__ __nv_bfloat16 g_wh[(size_t)H * FOUT * FIN];
__device__ __nv_bfloat16 g_hh[(size_t)H * BB * NN * FOUT];   // h bf16 hi

// ---- ldmatrix / mma.sync helpers (sm_80-era PTX, valid on plain sm_103) ---
__device__ __forceinline__ uint32_t smem_u32(const void* p) {
    uint32_t a;
    asm("{ .reg .u64 t; cvta.to.shared.u64 t, %1; cvt.u32.u64 %0, t; }" : "=r"(a) : "l"(p));
    return a;
}
#define LDMX4(r0, r1, r2, r3, a) \
    asm volatile("ldmatrix.sync.aligned.m8n8.x4.shared.b16 {%0,%1,%2,%3}, [%4];" \
                 : "=r"(r0), "=r"(r1), "=r"(r2), "=r"(r3) : "r"(a))
#define LDMX4T(r0, r1, r2, r3, a) \
    asm volatile("ldmatrix.sync.aligned.m8n8.x4.trans.shared.b16 {%0,%1,%2,%3}, [%4];" \
                 : "=r"(r0), "=r"(r1), "=r"(r2), "=r"(r3) : "r"(a))
#define MMA16816(d, a0, a1, a2, a3, b0, b1) \
    asm volatile("mma.sync.aligned.m16n8k16.row.col.f32.bf16.bf16.f32 " \
                 "{%0,%1,%2,%3},{%4,%5,%6,%7},{%8,%9},{%0,%1,%2,%3};" \
                 : "+f"((d)[0]), "+f"((d)[1]), "+f"((d)[2]), "+f"((d)[3]) \
                 : "r"(a0), "r"(a1), "r"(a2), "r"(a3), "r"(b0), "r"(b1))
#define CPA16(dst, src) \
    asm volatile("cp.async.cg.shared.global [%0], [%1], 16;" :: "r"(dst), "l"(src) : "memory")
#define CP_COMMIT() asm volatile("cp.async.commit_group;" ::: "memory")
#define CP_WAIT0()  asm volatile("cp.async.wait_group 0;" ::: "memory")
#define CP_WAIT1()  asm volatile("cp.async.wait_group 1;" ::: "memory")
// cvt d, a, b -> d.hi = a, d.lo = b
#define CVT_BF2(q, hi, lo) \
    asm("cvt.rn.bf16x2.f32 %0, %1, %2;" : "=r"(q) : "f"(hi), "f"(lo))

__device__ __forceinline__ uint32_t lmaddr(uint32_t base, int row, int chunk) {
    return base + row * 128 + (((chunk) ^ (row & 7)) << 4);
}

// ---------------------------------------------------------------------------
// Kernel 0: convert x, W to bf16 (hi only; wl term dropped per error budget)
// ---------------------------------------------------------------------------
__global__ __launch_bounds__(256) void split_kernel(const float* __restrict__ x,
                                                    const float* __restrict__ W)
{
    const size_t NX = (size_t)BB * NN * FIN;
    const size_t NW = (size_t)H * FOUT * FIN;
    size_t i = (size_t)blockIdx.x * 256 + threadIdx.x;
    size_t stride = (size_t)gridDim.x * 256;
    for (; i < NX + NW; i += stride) {
        if (i < NX) g_xh[i] = __float2bfloat16_rn(x[i]);
        else        g_wh[i - NX] = __float2bfloat16_rn(W[i - NX]);
    }
}

// ---------------------------------------------------------------------------
// Kernel 0b: c1/c2[hd][f] = sum_o W[hd][o][f] * a{1,2}[hd][o]  (exact fp32)
// ---------------------------------------------------------------------------
__global__ __launch_bounds__(512) void c12_kernel(const float* __restrict__ W,
                                                  const float* __restrict__ a1,
                                                  const float* __restrict__ a2)
{
    __shared__ float a1s[FOUT], a2s[FOUT];
    const int hd = blockIdx.x;
    const int f = threadIdx.x;
    for (int i = threadIdx.x; i < FOUT; i += 512) {
        a1s[i] = a1[hd * FOUT + i];
        a2s[i] = a2[hd * FOUT + i];
    }
    __syncthreads();
    const float* Wp = W + (size_t)hd * FOUT * FIN + f;
    float s1 = 0.f, s2 = 0.f;
#pragma unroll 4
    for (int o = 0; o < FOUT; o++) {
        float w = Wp[(size_t)o * FIN];
        s1 = fmaf(w, a1s[o], s1);
        s2 = fmaf(w, a2s[o], s2);
    }
    g_c1[hd * FIN + f] = s1;
    g_c2[hd * FIN + f] = s2;
}

// ---------------------------------------------------------------------------
// Kernel 0c: f1/f2[hd][r] = x[r] . c{1,2}[hd]  (warp per row, all heads)
// ---------------------------------------------------------------------------
__global__ __launch_bounds__(256) void f12x_kernel(const float* __restrict__ x)
{
    __shared__ float cs[2 * H * FIN];   // 32 KB
    for (int i = threadIdx.x; i < H * FIN; i += 256) {
        cs[i] = g_c1[i];
        cs[H * FIN + i] = g_c2[i];
    }
    __syncthreads();
    const int w = threadIdx.x >> 5, lane = threadIdx.x & 31;
    const int r = blockIdx.x * 8 + w;
    const float* xp = x + (size_t)r * FIN;
    float acc1[8], acc2[8];
#pragma unroll
    for (int hd = 0; hd < 8; hd++) { acc1[hd] = 0.f; acc2[hd] = 0.f; }
#pragma unroll
    for (int i = 0; i < 4; i++) {
        const int off = lane * 4 + i * 128;
        float4 xv = *(const float4*)(xp + off);
#pragma unroll
        for (int hd = 0; hd < 8; hd++) {
            float4 cv = *(const float4*)(cs + hd * FIN + off);
            acc1[hd] = fmaf(xv.x, cv.x, fmaf(xv.y, cv.y, fmaf(xv.z, cv.z, fmaf(xv.w, cv.w, acc1[hd]))));
            float4 dv = *(const float4*)(cs + H * FIN + hd * FIN + off);
            acc2[hd] = fmaf(xv.x, dv.x, fmaf(xv.y, dv.y, fmaf(xv.z, dv.z, fmaf(xv.w, dv.w, acc2[hd]))));
        }
    }
#pragma unroll
    for (int hd = 0; hd < 8; hd++) {
#pragma unroll
        for (int off = 16; off; off >>= 1) {
            acc1[hd] += __shfl_xor_sync(0xffffffffu, acc1[hd], off);
            acc2[hd] += __shfl_xor_sync(0xffffffffu, acc2[hd], off);
        }
    }
    if (lane == 0) {
#pragma unroll
        for (int hd = 0; hd < 8; hd++) {
            g_f1[hd * (BB * NN) + r] = acc1[hd];
            g_f2[hd * (BB * NN) + r] = acc2[hd];
        }
    }
}

// ---------------------------------------------------------------------------
// Kernel 1: h[hd] = xh @ Wh^T, cp.async double-buffered, store bf16 hi
// ---------------------------------------------------------------------------
#define G_A 0
#define G_B 16384
#define G_STAGE 32768
#define G_TOTAL 65536

__global__ __launch_bounds__(256) void gemm_h_mma(void)
{
    extern __shared__ char sm[];
    const uint32_t sb = smem_u32(sm);
    const int tid = threadIdx.x;
    const int wid = tid >> 5;
    const int lane = tid & 31;
    const int m0 = blockIdx.x * 128;
    const int o0 = blockIdx.y * 128;
    const int hd = blockIdx.z;
    const int warp_m = (wid & 3) * 32;
    const int warp_n = (wid >> 2) * 64;

    float d[2][8][4];
#pragma unroll
    for (int i = 0; i < 2; i++)
#pragma unroll
        for (int j = 0; j < 8; j++)
#pragma unroll
            for (int c = 0; c < 4; c++) d[i][j][c] = 0.f;

    const char* xh = (const char*)g_xh + (size_t)m0 * FIN * 2;
    const char* wh = (const char*)g_wh + ((size_t)hd * FOUT + o0) * FIN * 2;

    auto stage = [&](int kc, uint32_t off) {
#pragma unroll
        for (int it = 0; it < 4; it++) {
            int idx = tid + it * 256;
            int r = idx >> 3, ch = idx & 7;
            size_t gb = ((size_t)r * FIN + kc) * 2 + ch * 16;
            uint32_t so = off + r * 128 + ((ch ^ (r & 7)) << 4);
            CPA16(sb + G_A + so, xh + gb);
            CPA16(sb + G_B + so, wh + gb);
        }
    };

    const int lt = lane >> 3;
    const int lr = lane & 7;

    stage(0, 0);
    CP_COMMIT();

    // Hazard audit: at top of iter ck, CP_WAIT0 drains cp(ck); syncthreads
    // then orders all warps' compute(ck-1) reads of buf (ck-1)%2 before
    // cp(ck+1) overwrites that same buffer. One barrier per iteration.
    for (int ck = 0; ck < 8; ck++) {
        CP_WAIT0();
        __syncthreads();
        if (ck < 7) { stage((ck + 1) * 64, (ck & 1) ? 0u : (uint32_t)G_STAGE); CP_COMMIT(); }

        const uint32_t abase = sb + G_A + ((ck & 1) ? G_STAGE : 0);
        const uint32_t bbase = sb + G_B + ((ck & 1) ? G_STAGE : 0);

#pragma unroll
        for (int kk = 0; kk < 64; kk += 16) {
            const int kch = kk >> 3;
            uint32_t ah[2][4];
#pragma unroll
            for (int mi = 0; mi < 2; mi++) {
                int row = warp_m + mi * 16 + (lt & 1) * 8 + lr;
                LDMX4(ah[mi][0], ah[mi][1], ah[mi][2], ah[mi][3],
                      lmaddr(abase, row, kch + (lt >> 1)));
            }
#pragma unroll
            for (int pr = 0; pr < 4; pr++) {
                int row = warp_n + pr * 16 + (lt & 1) * 8 + lr;
                uint32_t bh0, bh1, bh2, bh3;
                LDMX4(bh0, bh1, bh2, bh3, lmaddr(bbase, row, kch + (lt >> 1)));
#pragma unroll
                for (int mi = 0; mi < 2; mi++) {
                    MMA16816(d[mi][2 * pr],     ah[mi][0], ah[mi][1], ah[mi][2], ah[mi][3], bh0, bh2);
                    MMA16816(d[mi][2 * pr + 1], ah[mi][0], ah[mi][1], ah[mi][2], ah[mi][3], bh1, bh3);
                }
            }
        }
    }

    // epilogue: store bf16 hi
    const int g = lane >> 2, t = lane & 3;
    const size_t hbase = (size_t)hd * BB * NN;
#pragma unroll
    for (int mi = 0; mi < 2; mi++) {
#pragma unroll
        for (int nj = 0; nj < 8; nj++) {
            int row = m0 + warp_m + mi * 16 + g;
            int col = o0 + warp_n + nj * 8 + 2 * t;
#pragma unroll
            for (int half = 0; half < 2; half++) {
                unsigned q;
                CVT_BF2(q, d[mi][nj][half * 2 + 1], d[mi][nj][half * 2]);
                size_t off = (hbase + row + half * 8) * FOUT + col;
                *(unsigned*)(g_hh + off) = q;
            }
        }
    }
}

// ---------------------------------------------------------------------------
// Kernel 3: attn via mma.sync, triple-buffered (one barrier per k-chunk)
// out-tile 64x256 per CTA, K=1024 in 64-chunks, 512 threads = 16 warps.
// ---------------------------------------------------------------------------
#define AS_HB0  0
#define AS_HB1  32768
#define AS_HB2  65536
#define AS_PB0  98304
#define AS_PB1  106496
#define AS_PB2  114688
#define AS_F2   122880
#define AS_MSK  126976
#define AS_F1   135168
#define AS_RED  135424
#define AS_RED2 137472
#define AS_INV  138496
#define AS_ROWM 138752
#define AS_LSE  139008
#define AS_TOTAL 139264

__global__ __launch_bounds__(512, 1) void attn_mma(const int* __restrict__ adj,
                                                   float* __restrict__ out)
{
    extern __shared__ char sm[];
    const uint32_t sb = smem_u32(sm);
    float*    f2_s  = (float*)(sm + AS_F2);
    float*    f1_s  = (float*)(sm + AS_F1);
    unsigned* mskw  = (unsigned*)(sm + AS_MSK);
    float*    red   = (float*)(sm + AS_RED);
    float*    red2  = (float*)(sm + AS_RED2);
    float*    inv_s = (float*)(sm + AS_INV);
    float*    rowm  = (float*)(sm + AS_ROWM);
    float*    lse   = (float*)(sm + AS_LSE);

    const int tid  = threadIdx.x;
    const int lane = tid & 31;
    const int wid  = tid >> 5;
    const int wm   = wid & 3;
    const int wn   = wid >> 2;
    const int b    = blockIdx.y;
    const int n0   = blockIdx.x * 64;

    const int prow8 = tid >> 3;       // 0..63
    const int k8    = tid & 7;

    // mask bits
    for (int pass = 0; pass < 128; pass++) {
        int row = pass >> 1;
        int m = ((pass & 1) << 9) + tid;
        int a = adj[((size_t)b * NN + n0 + row) * NN + m];
        unsigned w = __ballot_sync(0xffffffffu, a == 0);
        if (lane == 0) mskw[row * 32 + (m >> 5)] = w;
    }

    float tot[8][4];
#pragma unroll
    for (int j = 0; j < 8; j++)
#pragma unroll
        for (int c = 0; c < 4; c++) tot[j][c] = 0.f;

    const int g = lane >> 2, t4 = lane & 3;
    const int r0 = wm * 16 + g, r1 = r0 + 8;

    float psum = 0.f;

    auto cp_h = [&](const __nv_bfloat16* hsrc, int ck, int hOff) {
#pragma unroll
        for (int i = 0; i < 4; i++) {
            int idx = tid + 512 * i;
            int r = idx >> 5, cc = idx & 31;
            uint32_t dst = sb + hOff + r * 512 + ((cc ^ (r & 7)) << 4);
            CPA16(dst, (const char*)(hsrc + (size_t)(ck * 64 + r) * FOUT) + cc * 16);
        }
    };
    auto pgen = [&](int ck, int pOff, float f1v) {
        unsigned word = mskw[prow8 * 32 + (ck << 1) + (k8 >> 2)];
        unsigned byte = (word >> ((k8 & 3) << 3)) & 0xffu;
        const int kc = ck * 64;
        const float4 fa = *(const float4*)(f2_s + kc + k8 * 8);
        const float4 fb = *(const float4*)(f2_s + kc + k8 * 8 + 4);
        const float f2v[8] = {fa.x, fa.y, fa.z, fa.w, fb.x, fb.y, fb.z, fb.w};
        float pv[8];
#pragma unroll
        for (int j = 0; j < 8; j++) {
            float e = f1v + f2v[j];
            e = (e > 0.f) ? e : ALPHA * e;
            float p = ((byte >> j) & 1u) ? 0.f : __expf(e);
            pv[j] = p;
            psum += p;
        }
        uint4 q;
        CVT_BF2(q.x, pv[1], pv[0]);
        CVT_BF2(q.y, pv[3], pv[2]);
        CVT_BF2(q.z, pv[5], pv[4]);
        CVT_BF2(q.w, pv[7], pv[6]);
        *(uint4*)(sm + pOff + prow8 * 128 + ((k8 ^ (prow8 & 7)) << 4)) = q;
    };

    for (int hd = 0; hd < H; hd++) {
        const int base = (hd * BB + b) * NN;
        const __nv_bfloat16* hsrc = g_hh + (size_t)base * FOUT;

        __syncthreads();            // all warps finished previous head entirely
        f2_s[tid] = g_f2[base + tid];
        f2_s[tid + 512] = g_f2[base + tid + 512];
        if (tid < 64) f1_s[tid] = g_f1[base + n0 + tid];

        int hOffA = AS_HB0, hOffB = AS_HB1, hOffC = AS_HB2;
        int pOffA = AS_PB0, pOffB = AS_PB1, pOffC = AS_PB2;

        cp_h(hsrc, 0, hOffA); CP_COMMIT();
        __syncthreads();            // f1/f2 visible
        psum = 0.f;
        const float f1v = f1_s[prow8];
        pgen(0, pOffA, f1v);
        cp_h(hsrc, 1, hOffB); CP_COMMIT();

        float d[8][4];
#pragma unroll
        for (int j = 0; j < 8; j++)
#pragma unroll
            for (int c = 0; c < 4; c++) d[j][c] = 0.f;

        // Hazard audit (skew <= 1 iter, single barrier per iter, mod-3 bufs):
        //   pgen(ck+1) writes P[(ck+1)%3]; concurrent readers: MMA(ck) P[ck%3],
        //   lagging MMA(ck-1) P[(ck-1)%3] -> all distinct mod 3. Same for
        //   cp(ck+2) writing H[(ck+2)%3] vs MMA(ck)/MMA(ck-1) reads.
        for (int ck = 0; ck < 16; ck++) {
            if (ck == 15) { CP_WAIT0(); } else { CP_WAIT1(); }
            __syncthreads();        // p(ck) + h(ck) ready everywhere
            if (ck + 2 < 16) { cp_h(hsrc, ck + 2, hOffC); CP_COMMIT(); }
            if (ck + 1 < 16) pgen(ck + 1, pOffB, f1v);

            const uint32_t pbb = sb + pOffA;
            const uint32_t hbb = sb + hOffA;
#pragma unroll
            for (int ks = 0; ks < 64; ks += 16) {
                int prow = wm * 16 + (lane & 7) + ((lane >> 3) & 1) * 8;
                int pch = (ks >> 3) + (lane >> 4);
                uint32_t a0, a1, a2, a3;
                LDMX4(a0, a1, a2, a3, pbb + prow * 128 + ((pch ^ (prow & 7)) << 4));
                int hrow = ks + (lane & 7) + ((lane >> 3) & 1) * 8;
#pragma unroll
                for (int nt = 0; nt < 4; nt++) {
                    int hch = (wn << 3) + (nt << 1) + (lane >> 4);
                    uint32_t b0, b1, b2, b3;
                    LDMX4T(b0, b1, b2, b3, hbb + hrow * 512 + ((hch ^ (hrow & 7)) << 4));
                    MMA16816(d[2 * nt],     a0, a1, a2, a3, b0, b1);
                    MMA16816(d[2 * nt + 1], a0, a1, a2, a3, b2, b3);
                }
            }
            int t = hOffA; hOffA = hOffB; hOffB = hOffC; hOffC = t;
            t = pOffA; pOffA = pOffB; pOffB = pOffC; pOffC = t;
        }

        red[prow8 * 8 + k8] = psum;
        __syncthreads();
        if (tid < 64) {
            float s = 0.f;
#pragma unroll
            for (int j = 0; j < 8; j++) s += red[tid * 8 + j];
            inv_s[tid] = 1.f / s;
        }
        __syncthreads();

        const float i0 = inv_s[r0], i1 = inv_s[r1];
#pragma unroll
        for (int j = 0; j < 8; j++) {
            float v0 = d[j][0] * i0, v1 = d[j][1] * i0;
            float v2 = d[j][2] * i1, v3 = d[j][3] * i1;
            tot[j][0] += (v0 > 0.f) ? v0 : (__expf(v0) - 1.f);
            tot[j][1] += (v1 > 0.f) ? v1 : (__expf(v1) - 1.f);
            tot[j][2] += (v2 > 0.f) ? v2 : (__expf(v2) - 1.f);
            tot[j][3] += (v3 > 0.f) ? v3 : (__expf(v3) - 1.f);
        }
    }

    // ---- fused log_softmax over o (256 cols) for 64 rows ----
    __syncthreads();
    float vm0 = -3.0e38f, vm1 = -3.0e38f;
#pragma unroll
    for (int j = 0; j < 8; j++) {
        vm0 = fmaxf(vm0, fmaxf(tot[j][0], tot[j][1]));
        vm1 = fmaxf(vm1, fmaxf(tot[j][2], tot[j][3]));
    }
    vm0 = fmaxf(vm0, __shfl_xor_sync(0xffffffffu, vm0, 1));
    vm0 = fmaxf(vm0, __shfl_xor_sync(0xffffffffu, vm0, 2));
    vm1 = fmaxf(vm1, __shfl_xor_sync(0xffffffffu, vm1, 1));
    vm1 = fmaxf(vm1, __shfl_xor_sync(0xffffffffu, vm1, 2));
    if (t4 == 0) { red[r0 * 4 + wn] = vm0; red[r1 * 4 + wn] = vm1; }
    __syncthreads();
    if (tid < 64) {
        float v = red[tid * 4];
#pragma unroll
        for (int j = 1; j < 4; j++) v = fmaxf(v, red[tid * 4 + j]);
        rowm[tid] = v;
    }
    __syncthreads();
    const float rm0 = rowm[r0], rm1 = rowm[r1];
    float s0 = 0.f, s1 = 0.f;
#pragma unroll
    for (int j = 0; j < 8; j++) {
        s0 += __expf(tot[j][0] - rm0) + __expf(tot[j][1] - rm0);
        s1 += __expf(tot[j][2] - rm1) + __expf(tot[j][3] - rm1);
    }
    s0 += __shfl_xor_sync(0xffffffffu, s0, 1);
    s0 += __shfl_xor_sync(0xffffffffu, s0, 2);
    s1 += __shfl_xor_sync(0xffffffffu, s1, 1);
    s1 += __shfl_xor_sync(0xffffffffu, s1, 2);
    if (t4 == 0) { red2[r0 * 4 + wn] = s0; red2[r1 * 4 + wn] = s1; }
    __syncthreads();
    if (tid < 64) {
        float v = 0.f;
#pragma unroll
        for (int j = 0; j < 4; j++) v += red2[tid * 4 + j];
        lse[tid] = logf(v);
    }
    __syncthreads();
    const float c0 = rm0 + lse[r0], c1 = rm1 + lse[r1];
    float* o0p = out + ((size_t)b * NN + n0 + r0) * FOUT;
    float* o1p = out + ((size_t)b * NN + n0 + r1) * FOUT;
#pragma unroll
    for (int j = 0; j < 8; j++) {
        int col = wn * 64 + j * 8 + 2 * t4;
        *(float2*)(o0p + col) = make_float2(tot[j][0] - c0, tot[j][1] - c0);
        *(float2*)(o1p + col) = make_float2(tot[j][2] - c1, tot[j][3] - c1);
    }
}

// ---------------------------------------------------------------------------
extern "C" void kernel_launch(void* const* d_in, const int* in_sizes, int n_in,
                              void* d_out, int out_size)
{
    const float* x   = (const float*)d_in[0];
    const int*   adj = (const int*)d_in[1];
    const float* W   = (const float*)d_in[2];
    const float* a1  = (const float*)d_in[3];
    const float* a2  = (const float*)d_in[4];
    float* out = (float*)d_out;

    (void)in_sizes; (void)n_in; (void)out_size;

    cudaFuncSetAttribute(gemm_h_mma, cudaFuncAttributeMaxDynamicSharedMemorySize, G_TOTAL);
    cudaFuncSetAttribute(attn_mma, cudaFuncAttributeMaxDynamicSharedMemorySize, AS_TOTAL);

    split_kernel<<<2560, 256>>>(x, W);
    c12_kernel<<<8, 512>>>(W, a1, a2);
    f12x_kernel<<<1024, 256>>>(x);
    gemm_h_mma<<<dim3(64, 2, 8), 256, G_TOTAL>>>();
    attn_mma<<<dim3(16, 8), 512, AS_TOTAL>>>(adj, out);
}

// round 16
// speedup vs baseline: 7.8356x; 1.0735x over previous
#include <cuda_runtime.h>
#include <cuda_bf16.h>
#include <math.h>
#include <cstdint>

#define H    8
#define BB   8
#define NN   1024
#define FIN  512
#define FOUT 256
#define ALPHA 0.2f

// Scratch (device globals per harness allocation rules)
__device__ float g_f1[H * BB * NN];
__device__ float g_f2[H * BB * NN];
__device__ float g_c1[H * FIN];
__device__ float g_c2[H * FIN];
__device__ __nv_bfloat16 g_xh[(size_t)BB * NN * FIN];
__device__ __nv_bfloat16 g_wh[(size_t)H * FOUT * FIN];
__device__ __nv_bfloat16 g_hh[(size_t)H * BB * NN * FOUT];   // h bf16 hi

// ---- ldmatrix / mma.sync helpers (sm_80-era PTX, valid on plain sm_103) ---
__device__ __forceinline__ uint32_t smem_u32(const void* p) {
    uint32_t a;
    asm("{ .reg .u64 t; cvta.to.shared.u64 t, %1; cvt.u32.u64 %0, t; }" : "=r"(a) : "l"(p));
    return a;
}
#define LDMX4(r0, r1, r2, r3, a) \
    asm volatile("ldmatrix.sync.aligned.m8n8.x4.shared.b16 {%0,%1,%2,%3}, [%4];" \
                 : "=r"(r0), "=r"(r1), "=r"(r2), "=r"(r3) : "r"(a))
#define LDMX4T(r0, r1, r2, r3, a) \
    asm volatile("ldmatrix.sync.aligned.m8n8.x4.trans.shared.b16 {%0,%1,%2,%3}, [%4];" \
                 : "=r"(r0), "=r"(r1), "=r"(r2), "=r"(r3) : "r"(a))
#define MMA16816(d, a0, a1, a2, a3, b0, b1) \
    asm volatile("mma.sync.aligned.m16n8k16.row.col.f32.bf16.bf16.f32 " \
                 "{%0,%1,%2,%3},{%4,%5,%6,%7},{%8,%9},{%0,%1,%2,%3};" \
                 : "+f"((d)[0]), "+f"((d)[1]), "+f"((d)[2]), "+f"((d)[3]) \
                 : "r"(a0), "r"(a1), "r"(a2), "r"(a3), "r"(b0), "r"(b1))
#define CPA16(dst, src) \
    asm volatile("cp.async.cg.shared.global [%0], [%1], 16;" :: "r"(dst), "l"(src) : "memory")
#define CP_COMMIT() asm volatile("cp.async.commit_group;" ::: "memory")
#define CP_WAIT0()  asm volatile("cp.async.wait_group 0;" ::: "memory")
#define CP_WAIT1()  asm volatile("cp.async.wait_group 1;" ::: "memory")
// cvt d, a, b -> d.hi = a, d.lo = b
#define CVT_BF2(q, hi, lo) \
    asm("cvt.rn.bf16x2.f32 %0, %1, %2;" : "=r"(q) : "f"(hi), "f"(lo))

__device__ __forceinline__ uint32_t lmaddr(uint32_t base, int row, int chunk) {
    return base + row * 128 + (((chunk) ^ (row & 7)) << 4);
}

// ---------------------------------------------------------------------------
// Kernel 0: convert x, W to bf16 (hi only)
// ---------------------------------------------------------------------------
__global__ __launch_bounds__(256) void split_kernel(const float* __restrict__ x,
                                                    const float* __restrict__ W)
{
    const size_t NX = (size_t)BB * NN * FIN;
    const size_t NW = (size_t)H * FOUT * FIN;
    size_t i = (size_t)blockIdx.x * 256 + threadIdx.x;
    size_t stride = (size_t)gridDim.x * 256;
    for (; i < NX + NW; i += stride) {
        if (i < NX) g_xh[i] = __float2bfloat16_rn(x[i]);
        else        g_wh[i - NX] = __float2bfloat16_rn(W[i - NX]);
    }
}

// ---------------------------------------------------------------------------
// Kernel 0b: c1/c2[hd][f] = sum_o W[hd][o][f] * a{1,2}[hd][o]  (exact fp32)
// ---------------------------------------------------------------------------
__global__ __launch_bounds__(512) void c12_kernel(const float* __restrict__ W,
                                                  const float* __restrict__ a1,
                                                  const float* __restrict__ a2)
{
    __shared__ float a1s[FOUT], a2s[FOUT];
    const int hd = blockIdx.x;
    const int f = threadIdx.x;
    for (int i = threadIdx.x; i < FOUT; i += 512) {
        a1s[i] = a1[hd * FOUT + i];
        a2s[i] = a2[hd * FOUT + i];
    }
    __syncthreads();
    const float* Wp = W + (size_t)hd * FOUT * FIN + f;
    float s1 = 0.f, s2 = 0.f;
#pragma unroll 4
    for (int o = 0; o < FOUT; o++) {
        float w = Wp[(size_t)o * FIN];
        s1 = fmaf(w, a1s[o], s1);
        s2 = fmaf(w, a2s[o], s2);
    }
    g_c1[hd * FIN + f] = s1;
    g_c2[hd * FIN + f] = s2;
}

// ---------------------------------------------------------------------------
// Kernel 0c: f1/f2[hd][r] = x[r] . c{1,2}[hd]  (warp per row, all heads)
// ---------------------------------------------------------------------------
__global__ __launch_bounds__(256) void f12x_kernel(const float* __restrict__ x)
{
    __shared__ float cs[2 * H * FIN];   // 32 KB
    for (int i = threadIdx.x; i < H * FIN; i += 256) {
        cs[i] = g_c1[i];
        cs[H * FIN + i] = g_c2[i];
    }
    __syncthreads();
    const int w = threadIdx.x >> 5, lane = threadIdx.x & 31;
    const int r = blockIdx.x * 8 + w;
    const float* xp = x + (size_t)r * FIN;
    float acc1[8], acc2[8];
#pragma unroll
    for (int hd = 0; hd < 8; hd++) { acc1[hd] = 0.f; acc2[hd] = 0.f; }
#pragma unroll
    for (int i = 0; i < 4; i++) {
        const int off = lane * 4 + i * 128;
        float4 xv = *(const float4*)(xp + off);
#pragma unroll
        for (int hd = 0; hd < 8; hd++) {
            float4 cv = *(const float4*)(cs + hd * FIN + off);
            acc1[hd] = fmaf(xv.x, cv.x, fmaf(xv.y, cv.y, fmaf(xv.z, cv.z, fmaf(xv.w, cv.w, acc1[hd]))));
            float4 dv = *(const float4*)(cs + H * FIN + hd * FIN + off);
            acc2[hd] = fmaf(xv.x, dv.x, fmaf(xv.y, dv.y, fmaf(xv.z, dv.z, fmaf(xv.w, dv.w, acc2[hd]))));
        }
    }
#pragma unroll
    for (int hd = 0; hd < 8; hd++) {
#pragma unroll
        for (int off = 16; off; off >>= 1) {
            acc1[hd] += __shfl_xor_sync(0xffffffffu, acc1[hd], off);
            acc2[hd] += __shfl_xor_sync(0xffffffffu, acc2[hd], off);
        }
    }
    if (lane == 0) {
#pragma unroll
        for (int hd = 0; hd < 8; hd++) {
            g_f1[hd * (BB * NN) + r] = acc1[hd];
            g_f2[hd * (BB * NN) + r] = acc2[hd];
        }
    }
}

// ---------------------------------------------------------------------------
// Kernel 1: h[hd] = xh @ Wh^T, cp.async double-buffered, store bf16 hi
// ---------------------------------------------------------------------------
#define G_A 0
#define G_B 16384
#define G_STAGE 32768
#define G_TOTAL 65536

__global__ __launch_bounds__(256) void gemm_h_mma(void)
{
    extern __shared__ char sm[];
    const uint32_t sb = smem_u32(sm);
    const int tid = threadIdx.x;
    const int wid = tid >> 5;
    const int lane = tid & 31;
    const int m0 = blockIdx.x * 128;
    const int o0 = blockIdx.y * 128;
    const int hd = blockIdx.z;
    const int warp_m = (wid & 3) * 32;
    const int warp_n = (wid >> 2) * 64;

    float d[2][8][4];
#pragma unroll
    for (int i = 0; i < 2; i++)
#pragma unroll
        for (int j = 0; j < 8; j++)
#pragma unroll
            for (int c = 0; c < 4; c++) d[i][j][c] = 0.f;

    const char* xh = (const char*)g_xh + (size_t)m0 * FIN * 2;
    const char* wh = (const char*)g_wh + ((size_t)hd * FOUT + o0) * FIN * 2;

    auto stage = [&](int kc, uint32_t off) {
#pragma unroll
        for (int it = 0; it < 4; it++) {
            int idx = tid + it * 256;
            int r = idx >> 3, ch = idx & 7;
            size_t gb = ((size_t)r * FIN + kc) * 2 + ch * 16;
            uint32_t so = off + r * 128 + ((ch ^ (r & 7)) << 4);
            CPA16(sb + G_A + so, xh + gb);
            CPA16(sb + G_B + so, wh + gb);
        }
    };

    const int lt = lane >> 3;
    const int lr = lane & 7;

    stage(0, 0);
    CP_COMMIT();

    // Hazard audit: at top of iter ck, CP_WAIT0 drains cp(ck); syncthreads
    // then orders all warps' compute(ck-1) reads of buf (ck-1)%2 before
    // cp(ck+1) overwrites that same buffer. One barrier per iteration.
    for (int ck = 0; ck < 8; ck++) {
        CP_WAIT0();
        __syncthreads();
        if (ck < 7) { stage((ck + 1) * 64, (ck & 1) ? 0u : (uint32_t)G_STAGE); CP_COMMIT(); }

        const uint32_t abase = sb + G_A + ((ck & 1) ? G_STAGE : 0);
        const uint32_t bbase = sb + G_B + ((ck & 1) ? G_STAGE : 0);

#pragma unroll
        for (int kk = 0; kk < 64; kk += 16) {
            const int kch = kk >> 3;
            uint32_t ah[2][4];
#pragma unroll
            for (int mi = 0; mi < 2; mi++) {
                int row = warp_m + mi * 16 + (lt & 1) * 8 + lr;
                LDMX4(ah[mi][0], ah[mi][1], ah[mi][2], ah[mi][3],
                      lmaddr(abase, row, kch + (lt >> 1)));
            }
#pragma unroll
            for (int pr = 0; pr < 4; pr++) {
                int row = warp_n + pr * 16 + (lt & 1) * 8 + lr;
                uint32_t bh0, bh1, bh2, bh3;
                LDMX4(bh0, bh1, bh2, bh3, lmaddr(bbase, row, kch + (lt >> 1)));
#pragma unroll
                for (int mi = 0; mi < 2; mi++) {
                    MMA16816(d[mi][2 * pr],     ah[mi][0], ah[mi][1], ah[mi][2], ah[mi][3], bh0, bh2);
                    MMA16816(d[mi][2 * pr + 1], ah[mi][0], ah[mi][1], ah[mi][2], ah[mi][3], bh1, bh3);
                }
            }
        }
    }

    // epilogue: store bf16 hi
    const int g = lane >> 2, t = lane & 3;
    const size_t hbase = (size_t)hd * BB * NN;
#pragma unroll
    for (int mi = 0; mi < 2; mi++) {
#pragma unroll
        for (int nj = 0; nj < 8; nj++) {
            int row = m0 + warp_m + mi * 16 + g;
            int col = o0 + warp_n + nj * 8 + 2 * t;
#pragma unroll
            for (int half = 0; half < 2; half++) {
                unsigned q;
                CVT_BF2(q, d[mi][nj][half * 2 + 1], d[mi][nj][half * 2]);
                size_t off = (hbase + row + half * 8) * FOUT + col;
                *(unsigned*)(g_hh + off) = q;
            }
        }
    }
}

// ---------------------------------------------------------------------------
// Kernel 3: attn via mma.sync, triple-buffered, warp layout 2m x 8n
// (minimizes LDS traffic: 2*32KB(h) + 8*8KB(p) = 128KB per k-chunk vs 160KB
//  for 4x4). out-tile 64x256 per CTA, K=1024 in 64-chunks, 512 thr/16 warps.
// ---------------------------------------------------------------------------
#define AS_HB0  0
#define AS_HB1  32768
#define AS_HB2  65536
#define AS_PB0  98304
#define AS_PB1  106496
#define AS_PB2  114688
#define AS_F2   122880
#define AS_MSK  126976
#define AS_F1   135168
#define AS_RED  135424
#define AS_RED2 137472
#define AS_INV  139520
#define AS_ROWM 139776
#define AS_LSE  140032
#define AS_TOTAL 140288

__global__ __launch_bounds__(512, 1) void attn_mma(const int* __restrict__ adj,
                                                   float* __restrict__ out)
{
    extern __shared__ char sm[];
    const uint32_t sb = smem_u32(sm);
    float*    f2_s  = (float*)(sm + AS_F2);
    float*    f1_s  = (float*)(sm + AS_F1);
    unsigned* mskw  = (unsigned*)(sm + AS_MSK);
    float*    red   = (float*)(sm + AS_RED);   // [64][8]
    float*    red2  = (float*)(sm + AS_RED2);  // [64][8]
    float*    inv_s = (float*)(sm + AS_INV);
    float*    rowm  = (float*)(sm + AS_ROWM);
    float*    lse   = (float*)(sm + AS_LSE);

    const int tid  = threadIdx.x;
    const int lane = tid & 31;
    const int wid  = tid >> 5;
    const int wm   = wid & 1;         // 2 m-groups of 32 rows
    const int wn   = wid >> 1;        // 8 n-groups of 32 cols
    const int b    = blockIdx.y;
    const int n0   = blockIdx.x * 64;

    const int prow8 = tid >> 3;       // 0..63
    const int k8    = tid & 7;

    // ---- hoisted ldmatrix addressing constants (ks ≡ 0 mod 8 ⇒ row&7 = lane&7)
    const int l7   = lane & 7;
    const int lrow = l7 + ((lane >> 3) & 1) * 8;   // 0..15 row-in-tile
    const int lch  = lane >> 4;                    // 0..1 col-chunk half
    uint32_t arow_off[2], axoff[4], bxoff[2];
#pragma unroll
    for (int mi = 0; mi < 2; mi++)
        arow_off[mi] = (uint32_t)((wm * 32 + mi * 16 + lrow) * 128);
#pragma unroll
    for (int k = 0; k < 4; k++)
        axoff[k] = (uint32_t)((((k << 1) + lch) ^ l7) << 4);
#pragma unroll
    for (int nt = 0; nt < 2; nt++)
        bxoff[nt] = (uint32_t)(((wn * 4 + nt * 2 + lch) ^ l7) << 4);
    const uint32_t brow_off = (uint32_t)(lrow * 512);

    // mask bits
    for (int pass = 0; pass < 128; pass++) {
        int row = pass >> 1;
        int m = ((pass & 1) << 9) + tid;
        int a = adj[((size_t)b * NN + n0 + row) * NN + m];
        unsigned w = __ballot_sync(0xffffffffu, a == 0);
        if (lane == 0) mskw[row * 32 + (m >> 5)] = w;
    }

    float tot[2][4][4];
#pragma unroll
    for (int mi = 0; mi < 2; mi++)
#pragma unroll
        for (int j = 0; j < 4; j++)
#pragma unroll
            for (int c = 0; c < 4; c++) tot[mi][j][c] = 0.f;

    const int g = lane >> 2, t4 = lane & 3;

    float psum = 0.f;

    auto cp_h = [&](const __nv_bfloat16* hsrc, int ck, int hOff) {
#pragma unroll
        for (int i = 0; i < 4; i++) {
            int idx = tid + 512 * i;
            int r = idx >> 5, cc = idx & 31;
            uint32_t dst = sb + hOff + r * 512 + ((cc ^ (r & 7)) << 4);
            CPA16(dst, (const char*)(hsrc + (size_t)(ck * 64 + r) * FOUT) + cc * 16);
        }
    };
    auto pgen = [&](int ck, int pOff, float f1v) {
        unsigned word = mskw[prow8 * 32 + (ck << 1) + (k8 >> 2)];
        unsigned byte = (word >> ((k8 & 3) << 3)) & 0xffu;
        const int kc = ck * 64;
        const float4 fa = *(const float4*)(f2_s + kc + k8 * 8);
        const float4 fb = *(const float4*)(f2_s + kc + k8 * 8 + 4);
        const float f2v[8] = {fa.x, fa.y, fa.z, fa.w, fb.x, fb.y, fb.z, fb.w};
        float pv[8];
#pragma unroll
        for (int j = 0; j < 8; j++) {
            float e = f1v + f2v[j];
            e = (e > 0.f) ? e : ALPHA * e;
            float p = ((byte >> j) & 1u) ? 0.f : __expf(e);
            pv[j] = p;
            psum += p;
        }
        uint4 q;
        CVT_BF2(q.x, pv[1], pv[0]);
        CVT_BF2(q.y, pv[3], pv[2]);
        CVT_BF2(q.z, pv[5], pv[4]);
        CVT_BF2(q.w, pv[7], pv[6]);
        *(uint4*)(sm + pOff + prow8 * 128 + ((k8 ^ (prow8 & 7)) << 4)) = q;
    };

    for (int hd = 0; hd < H; hd++) {
        const int base = (hd * BB + b) * NN;
        const __nv_bfloat16* hsrc = g_hh + (size_t)base * FOUT;

        __syncthreads();            // all warps finished previous head entirely
        f2_s[tid] = g_f2[base + tid];
        f2_s[tid + 512] = g_f2[base + tid + 512];
        if (tid < 64) f1_s[tid] = g_f1[base + n0 + tid];

        int hOffA = AS_HB0, hOffB = AS_HB1, hOffC = AS_HB2;
        int pOffA = AS_PB0, pOffB = AS_PB1, pOffC = AS_PB2;

        cp_h(hsrc, 0, hOffA); CP_COMMIT();
        __syncthreads();            // f1/f2 visible
        psum = 0.f;
        const float f1v = f1_s[prow8];
        pgen(0, pOffA, f1v);
        cp_h(hsrc, 1, hOffB); CP_COMMIT();

        float d[2][4][4];
#pragma unroll
        for (int mi = 0; mi < 2; mi++)
#pragma unroll
            for (int j = 0; j < 4; j++)
#pragma unroll
                for (int c = 0; c < 4; c++) d[mi][j][c] = 0.f;

        // Hazard audit (skew <= 1 iter, single barrier per iter, mod-3 bufs):
        //   pgen(ck+1) writes P[(ck+1)%3]; concurrent readers: MMA(ck) P[ck%3],
        //   lagging MMA(ck-1) P[(ck-1)%3] -> all distinct mod 3. Same for
        //   cp(ck+2) writing H[(ck+2)%3] vs MMA(ck)/MMA(ck-1) reads.
        for (int ck = 0; ck < 16; ck++) {
            if (ck == 15) { CP_WAIT0(); } else { CP_WAIT1(); }
            __syncthreads();        // p(ck) + h(ck) ready everywhere
            if (ck + 2 < 16) { cp_h(hsrc, ck + 2, hOffC); CP_COMMIT(); }
            if (ck + 1 < 16) pgen(ck + 1, pOffB, f1v);

            const uint32_t pbb = sb + pOffA;
            const uint32_t hbb = sb + hOffA + brow_off;
#pragma unroll
            for (int ks = 0; ks < 64; ks += 16) {
                uint32_t a[2][4];
#pragma unroll
                for (int mi = 0; mi < 2; mi++)
                    LDMX4(a[mi][0], a[mi][1], a[mi][2], a[mi][3],
                          pbb + arow_off[mi] + axoff[ks >> 4]);
#pragma unroll
                for (int nt = 0; nt < 2; nt++) {
                    uint32_t b0, b1, b2, b3;
                    LDMX4T(b0, b1, b2, b3, hbb + ks * 512 + bxoff[nt]);
#pragma unroll
                    for (int mi = 0; mi < 2; mi++) {
                        MMA16816(d[mi][2 * nt],     a[mi][0], a[mi][1], a[mi][2], a[mi][3], b0, b1);
                        MMA16816(d[mi][2 * nt + 1], a[mi][0], a[mi][1], a[mi][2], a[mi][3], b2, b3);
                    }
                }
            }
            int t = hOffA; hOffA = hOffB; hOffB = hOffC; hOffC = t;
            t = pOffA; pOffA = pOffB; pOffB = pOffC; pOffC = t;
        }

        red[prow8 * 8 + k8] = psum;
        __syncthreads();
        if (tid < 64) {
            float s = 0.f;
#pragma unroll
            for (int j = 0; j < 8; j++) s += red[tid * 8 + j];
            inv_s[tid] = 1.f / s;
        }
        __syncthreads();

#pragma unroll
        for (int mi = 0; mi < 2; mi++) {
            const int rb = wm * 32 + mi * 16 + g;
            const float i0 = inv_s[rb], i1 = inv_s[rb + 8];
#pragma unroll
            for (int j = 0; j < 4; j++) {
                float v0 = d[mi][j][0] * i0, v1 = d[mi][j][1] * i0;
                float v2 = d[mi][j][2] * i1, v3 = d[mi][j][3] * i1;
                tot[mi][j][0] += (v0 > 0.f) ? v0 : (__expf(v0) - 1.f);
                tot[mi][j][1] += (v1 > 0.f) ? v1 : (__expf(v1) - 1.f);
                tot[mi][j][2] += (v2 > 0.f) ? v2 : (__expf(v2) - 1.f);
                tot[mi][j][3] += (v3 > 0.f) ? v3 : (__expf(v3) - 1.f);
            }
        }
    }

    // ---- fused log_softmax over o (256 cols) for 64 rows ----
    // thread owns rows r(mi,half) = wm*32 + mi*16 + half*8 + g, 8 vals each
    __syncthreads();
#pragma unroll
    for (int mi = 0; mi < 2; mi++) {
#pragma unroll
        for (int half = 0; half < 2; half++) {
            float vm = -3.0e38f;
#pragma unroll
            for (int j = 0; j < 4; j++)
                vm = fmaxf(vm, fmaxf(tot[mi][j][half * 2], tot[mi][j][half * 2 + 1]));
            vm = fmaxf(vm, __shfl_xor_sync(0xffffffffu, vm, 1));
            vm = fmaxf(vm, __shfl_xor_sync(0xffffffffu, vm, 2));
            if (t4 == 0) red[(wm * 32 + mi * 16 + half * 8 + g) * 8 + wn] = vm;
        }
    }
    __syncthreads();
    if (tid < 64) {
        float v = red[tid * 8];
#pragma unroll
        for (int j = 1; j < 8; j++) v = fmaxf(v, red[tid * 8 + j]);
        rowm[tid] = v;
    }
    __syncthreads();
#pragma unroll
    for (int mi = 0; mi < 2; mi++) {
#pragma unroll
        for (int half = 0; half < 2; half++) {
            const float rm = rowm[wm * 32 + mi * 16 + half * 8 + g];
            float s = 0.f;
#pragma unroll
            for (int j = 0; j < 4; j++)
                s += __expf(tot[mi][j][half * 2] - rm) + __expf(tot[mi][j][half * 2 + 1] - rm);
            s += __shfl_xor_sync(0xffffffffu, s, 1);
            s += __shfl_xor_sync(0xffffffffu, s, 2);
            if (t4 == 0) red2[(wm * 32 + mi * 16 + half * 8 + g) * 8 + wn] = s;
        }
    }
    __syncthreads();
    if (tid < 64) {
        float v = 0.f;
#pragma unroll
        for (int j = 0; j < 8; j++) v += red2[tid * 8 + j];
        lse[tid] = logf(v);
    }
    __syncthreads();
#pragma unroll
    for (int mi = 0; mi < 2; mi++) {
#pragma unroll
        for (int half = 0; half < 2; half++) {
            const int row = wm * 32 + mi * 16 + half * 8 + g;
            const float c = rowm[row] + lse[row];
            float* op = out + ((size_t)b * NN + n0 + row) * FOUT;
#pragma unroll
            for (int j = 0; j < 4; j++) {
                int col = wn * 32 + j * 8 + 2 * t4;
                *(float2*)(op + col) = make_float2(tot[mi][j][half * 2] - c,
                                                   tot[mi][j][half * 2 + 1] - c);
            }
        }
    }
}

// ---------------------------------------------------------------------------
extern "C" void kernel_launch(void* const* d_in, const int* in_sizes, int n_in,
                              void* d_out, int out_size)
{
    const float* x   = (const float*)d_in[0];
    const int*   adj = (const int*)d_in[1];
    const float* W   = (const float*)d_in[2];
    const float* a1  = (const float*)d_in[3];
    const float* a2  = (const float*)d_in[4];
    float* out = (float*)d_out;

    (void)in_sizes; (void)n_in; (void)out_size;

    cudaFuncSetAttribute(gemm_h_mma, cudaFuncAttributeMaxDynamicSharedMemorySize, G_TOTAL);
    cudaFuncSetAttribute(attn_mma, cudaFuncAttributeMaxDynamicSharedMemorySize, AS_TOTAL);

    split_kernel<<<2560, 256>>>(x, W);
    c12_kernel<<<8, 512>>>(W, a1, a2);
    f12x_kernel<<<1024, 256>>>(x);
    gemm_h_mma<<<dim3(64, 2, 8), 256, G_TOTAL>>>();
    attn_mma<<<dim3(16, 8), 512, AS_TOTAL>>>(adj, out);
}